// round 12
// baseline (speedup 1.0000x reference)
#include <cuda_runtime.h>
#include <cuda_bf16.h>
#include <math.h>
#include <cstdint>

// ---------------- problem constants ----------------
#define NTOK 200704           // 4*16*56*56

// ---------------- scratch (static device globals; allowed) ----------------
__device__ __align__(16) float g_x1  [NTOK*96];
__device__ __align__(16) float g_x2  [NTOK*96];
__device__ __align__(16) float g_part2[588*4];
__device__ __align__(16) float g_stats[16*2];
__device__ __align__(16) __nv_bfloat16 g_convb[NTOK*96];
__device__ __align__(16) __nv_bfloat16 g_qkvb[NTOK*288];
__device__ __align__(16) __nv_bfloat16 g_xnb [NTOK*96];
__device__ __align__(16) __nv_bfloat16 g_x1b [NTOK*96];
__device__ __align__(16) __nv_bfloat16 g_wq  [288*96];
__device__ __align__(16) __nv_bfloat16 g_wp  [96*96];
__device__ __align__(16) __nv_bfloat16 g_wc  [96*96];
__device__ __align__(16) __nv_bfloat16 g_w1  [384*96];
__device__ __align__(16) __nv_bfloat16 g_w2  [96*384];
__device__ __align__(16) __nv_bfloat16 g_wc3 [96*864];

// ---------------- warp-MMA helpers ------------------------------------------
__device__ __forceinline__ uint32_t smem_u32(const void* p) {
    uint32_t a;
    asm("{ .reg .u64 t; cvta.to.shared.u64 t, %1; cvt.u32.u64 %0, t; }" : "=r"(a) : "l"(p));
    return a;
}
__device__ __forceinline__ void ldsm_x4(uint32_t* r, uint32_t addr) {
    asm volatile("ldmatrix.sync.aligned.m8n8.x4.shared.b16 {%0,%1,%2,%3}, [%4];"
        : "=r"(r[0]), "=r"(r[1]), "=r"(r[2]), "=r"(r[3]) : "r"(addr));
}
__device__ __forceinline__ void mma16816(float* d, const uint32_t* a, const uint32_t* b) {
    asm volatile(
        "mma.sync.aligned.m16n8k16.row.col.f32.bf16.bf16.f32 "
        "{%0,%1,%2,%3}, {%4,%5,%6,%7}, {%8,%9}, {%0,%1,%2,%3};"
        : "+f"(d[0]), "+f"(d[1]), "+f"(d[2]), "+f"(d[3])
        : "r"(a[0]), "r"(a[1]), "r"(a[2]), "r"(a[3]), "r"(b[0]), "r"(b[1]));
}
__device__ __forceinline__ float gelu_exact(float v) {
    return 0.5f * v * (1.f + erff(v * 0.70710678118654752f));
}

// ---------------- tensor-core GEMM (K=96), M-tile 128 -----------------------
// PROLOG 1: A fp32 + fused LayerNorm -> bf16. EPI 4: bf16 store.
template<int NCH, int EPI, int PROLOG>
__global__ __launch_bounds__(256)
void tgemm(const void* __restrict__ Ax, const __nv_bfloat16* __restrict__ W,
           const float* __restrict__ bias, const float* __restrict__ resid,
           void* __restrict__ outv, __nv_bfloat16* __restrict__ out2,
           const float* __restrict__ lnw, const float* __restrict__ lnb) {
    constexpr int PITCH = 104;
    constexpr int NOtot = 96 * NCH;
    __shared__ __align__(16) __nv_bfloat16 As[128 * PITCH];
    __shared__ __align__(16) __nv_bfloat16 Bs[96 * PITCH];
    const int tid = threadIdx.x;
    const int wid = tid >> 5, lane = tid & 31;
    const int warpM = wid & 3, warpN = wid >> 2;
    const long row0 = (long)blockIdx.x * 128;

    if (PROLOG == 0) {
        const __nv_bfloat16* A = (const __nv_bfloat16*)Ax;
        #pragma unroll
        for (int it = 0; it < 6; it++) {
            int idx = tid + it * 256;
            int r = idx / 12, k = (idx % 12) * 8;
            uint4 v = *(const uint4*)(A + (row0 + r) * 96 + k);
            *(uint4*)(&As[r * PITCH + k]) = v;
        }
    } else {
        const int r = tid >> 1, half = tid & 1;
        const float* xr = (const float*)Ax + (row0 + r) * 96 + half * 48;
        float vb[48];
        float s = 0.f, q2 = 0.f;
        #pragma unroll
        for (int i = 0; i < 12; i++) {
            float4 f = *(const float4*)(xr + i * 4);
            vb[i*4] = f.x; vb[i*4+1] = f.y; vb[i*4+2] = f.z; vb[i*4+3] = f.w;
            s  += f.x + f.y + f.z + f.w;
            q2 += f.x*f.x + f.y*f.y + f.z*f.z + f.w*f.w;
        }
        s  += __shfl_xor_sync(0xFFFFFFFFu, s, 1);
        q2 += __shfl_xor_sync(0xFFFFFFFFu, q2, 1);
        float mu = s * (1.f / 96.f);
        float var = q2 * (1.f / 96.f) - mu * mu;
        float rs = rsqrtf(var + 1e-5f);
        #pragma unroll
        for (int j = 0; j < 48; j += 2) {
            int c = half * 48 + j;
            float n0 = (vb[j]   - mu) * rs * lnw[c]     + lnb[c];
            float n1 = (vb[j+1] - mu) * rs * lnw[c + 1] + lnb[c + 1];
            *(__nv_bfloat162*)(&As[r * PITCH + c]) = __floats2bfloat162_rn(n0, n1);
        }
    }

    const uint32_t smA = smem_u32(As), smB = smem_u32(Bs);
    const int t8 = lane & 7, tq = lane >> 3;
    const int rowA_base = warpM * 32 + t8 + (tq & 1) * 8;
    const int koffA = (tq >> 1) * 8;
    uint32_t offA[2];
    #pragma unroll
    for (int mf = 0; mf < 2; mf++)
        offA[mf] = smA + (uint32_t)(((rowA_base + mf * 16) * PITCH + koffA) * 2);
    const int rowB_base = warpN * 48 + t8 + (tq >> 1) * 8;
    const int koffB = (tq & 1) * 8;
    uint32_t offB[3];
    #pragma unroll
    for (int np = 0; np < 3; np++)
        offB[np] = smB + (uint32_t)(((rowB_base + np * 16) * PITCH + koffB) * 2);
    const int g = lane >> 2, tig = lane & 3;

    #pragma unroll
    for (int nc = 0; nc < NCH; nc++) {
        const int col0 = nc * 96;
        if (nc) __syncthreads();
        for (int idx = tid; idx < 96 * 12; idx += 256) {
            int n = idx / 12, k = (idx % 12) * 8;
            uint4 v = *(const uint4*)(W + (long)(col0 + n) * 96 + k);
            *(uint4*)(&Bs[n * PITCH + k]) = v;
        }
        __syncthreads();

        float acc[2][6][4];
        #pragma unroll
        for (int i = 0; i < 2; i++)
            #pragma unroll
            for (int j = 0; j < 6; j++)
                #pragma unroll
                for (int q = 0; q < 4; q++) acc[i][j][q] = 0.f;
        #pragma unroll
        for (int ks = 0; ks < 6; ks++) {
            uint32_t af[2][4], bf[3][4];
            ldsm_x4(af[0], offA[0] + ks * 32);
            ldsm_x4(af[1], offA[1] + ks * 32);
            ldsm_x4(bf[0], offB[0] + ks * 32);
            ldsm_x4(bf[1], offB[1] + ks * 32);
            ldsm_x4(bf[2], offB[2] + ks * 32);
            #pragma unroll
            for (int mf = 0; mf < 2; mf++)
                #pragma unroll
                for (int np = 0; np < 3; np++) {
                    mma16816(acc[mf][np * 2 + 0], af[mf], &bf[np][0]);
                    mma16816(acc[mf][np * 2 + 1], af[mf], &bf[np][2]);
                }
        }

        #pragma unroll
        for (int mf = 0; mf < 2; mf++) {
            #pragma unroll
            for (int nf = 0; nf < 6; nf++) {
                int col = col0 + warpN * 48 + nf * 8 + tig * 2;
                #pragma unroll
                for (int h = 0; h < 2; h++) {
                    long row = row0 + warpM * 32 + mf * 16 + g + h * 8;
                    float v0 = acc[mf][nf][h * 2 + 0];
                    float v1 = acc[mf][nf][h * 2 + 1];
                    *(__nv_bfloat162*)((__nv_bfloat16*)outv + row * NOtot + col) = __floats2bfloat162_rn(v0, v1);
                }
            }
        }
    }
}

// ---------------- fused attention + proj GEMM -------------------------------
// One block per window (2048). Stage k/v (98x96) + wp in smem, compute the
// multi-dilate attention into a 98x96 smem tile, then proj GEMM + residual.
__global__ __launch_bounds__(256)
void attnproj_kernel(const __nv_bfloat16* __restrict__ qkv, const __nv_bfloat16* __restrict__ wp,
                     const float* __restrict__ bias, const float* __restrict__ x,
                     float* __restrict__ x1, __nv_bfloat16* __restrict__ x1b) {
    constexpr int PITCH = 104;
    extern __shared__ __align__(16) char sma[];
    __nv_bfloat16* As = (__nv_bfloat16*)sma;                  // 128*104 = 26624B
    __nv_bfloat16* Bs = (__nv_bfloat16*)(sma + 26624);        // 96*104  = 19968B
    __nv_bfloat16* ks = (__nv_bfloat16*)(sma + 46592);        // 98*96   = 18816B
    __nv_bfloat16* vs = (__nv_bfloat16*)(sma + 65408);        // 98*96
    __shared__ int toks[98];
    const int win = blockIdx.x;
    const int tid = threadIdx.x;
    const int wid = tid >> 5, lane = tid & 31;
    const int warpM = wid & 3, warpN = wid >> 2;

    if (tid < 98) {
        int b = win >> 9, dq = (win >> 6) & 7, hq = (win >> 3) & 7, wq = win & 7;
        int wd = tid / 49, rem = tid % 49, wh = rem / 7, ww = rem % 7;
        toks[tid] = ((b * 16 + dq * 2 + wd) * 56 + hq * 7 + wh) * 56 + wq * 7 + ww;
    }
    __syncthreads();
    // stage k/v (full 96 ch per token) and proj weights
    for (int idx = tid; idx < 98 * 24; idx += 256) {
        int n = idx / 24, sub = idx % 24;
        int isv = sub / 12, c8 = (sub % 12) * 8;
        uint4 v = *(const uint4*)(qkv + (long)toks[n] * 288 + 96 + isv * 96 + c8);
        *(uint4*)((isv ? vs : ks) + n * 96 + c8) = v;
    }
    for (int idx = tid; idx < 96 * 12; idx += 256) {
        int n = idx / 12, k = (idx % 12) * 8;
        uint4 v = *(const uint4*)(wp + n * 96 + k);
        *(uint4*)(&Bs[n * PITCH + k]) = v;
    }
    __syncthreads();

    // attention: 98 tokens x 6 (dil,head) tasks
    for (int task = tid; task < 588; task += 256) {
        int n = task / 6, dh = task % 6;
        int dil = (dh >> 1) + 1;
        int choff = (dh >> 1) * 32 + (dh & 1) * 16;
        long qbase = (long)toks[n] * 288 + choff;
        float q[16];
        {
            uint4 qa = *(const uint4*)(qkv + qbase);
            uint4 qb = *(const uint4*)(qkv + qbase + 8);
            const __nv_bfloat162* qp = (const __nv_bfloat162*)&qa;
            #pragma unroll
            for (int i = 0; i < 4; i++) {
                float2 f = __bfloat1622float2(qp[i]);
                q[i * 2] = f.x; q[i * 2 + 1] = f.y;
            }
            qp = (const __nv_bfloat162*)&qb;
            #pragma unroll
            for (int i = 0; i < 4; i++) {
                float2 f = __bfloat1622float2(qp[i]);
                q[8 + i * 2] = f.x; q[8 + i * 2 + 1] = f.y;
            }
        }
        float lr[3]; int mm[3];
        #pragma unroll
        for (int j = 0; j < 3; j++) {
            int m = n + (j - 1) * dil;
            mm[j] = m;
            float s = 0.f;
            if (m >= 0 && m < 98) {
                const __nv_bfloat162* kr = (const __nv_bfloat162*)&ks[m * 96 + choff];
                #pragma unroll
                for (int c = 0; c < 8; c++) {
                    float2 f = __bfloat1622float2(kr[c]);
                    s += q[c * 2] * f.x + q[c * 2 + 1] * f.y;
                }
            }
            lr[j] = s * 0.25f;
        }
        float mx = fmaxf(0.f, fmaxf(lr[0], fmaxf(lr[1], lr[2])));
        float e[3];
        e[0] = expf(lr[0] - mx); e[1] = expf(lr[1] - mx); e[2] = expf(lr[2] - mx);
        float denom = 6.f * expf(-mx) + e[0] + e[1] + e[2];
        float o[16];
        #pragma unroll
        for (int c = 0; c < 16; c++) o[c] = 0.f;
        #pragma unroll
        for (int j = 0; j < 3; j++) {
            int m = mm[j];
            if (m >= 0 && m < 98) {
                float a = e[j] / denom;
                const __nv_bfloat162* vr = (const __nv_bfloat162*)&vs[m * 96 + choff];
                #pragma unroll
                for (int c = 0; c < 8; c++) {
                    float2 f = __bfloat1622float2(vr[c]);
                    o[c * 2]     += a * f.x;
                    o[c * 2 + 1] += a * f.y;
                }
            }
        }
        #pragma unroll
        for (int c = 0; c < 8; c++)
            *(__nv_bfloat162*)(&As[n * PITCH + choff + c * 2]) = __floats2bfloat162_rn(o[c * 2], o[c * 2 + 1]);
    }
    __syncthreads();

    // proj GEMM: 128-row tile (rows >= 98 are garbage, masked at store)
    const uint32_t smA = smem_u32(As), smB = smem_u32(Bs);
    const int t8 = lane & 7, tq = lane >> 3;
    const int rowA_base = warpM * 32 + t8 + (tq & 1) * 8;
    const int koffA = (tq >> 1) * 8;
    uint32_t offA[2];
    #pragma unroll
    for (int mf = 0; mf < 2; mf++)
        offA[mf] = smA + (uint32_t)(((rowA_base + mf * 16) * PITCH + koffA) * 2);
    const int rowB_base = warpN * 48 + t8 + (tq >> 1) * 8;
    const int koffB = (tq & 1) * 8;
    uint32_t offB[3];
    #pragma unroll
    for (int np = 0; np < 3; np++)
        offB[np] = smB + (uint32_t)(((rowB_base + np * 16) * PITCH + koffB) * 2);
    const int g = lane >> 2, tig = lane & 3;

    float acc[2][6][4];
    #pragma unroll
    for (int i = 0; i < 2; i++)
        #pragma unroll
        for (int j = 0; j < 6; j++)
            #pragma unroll
            for (int q = 0; q < 4; q++) acc[i][j][q] = 0.f;
    #pragma unroll
    for (int ksb = 0; ksb < 6; ksb++) {
        uint32_t af[2][4], bf[3][4];
        ldsm_x4(af[0], offA[0] + ksb * 32);
        ldsm_x4(af[1], offA[1] + ksb * 32);
        ldsm_x4(bf[0], offB[0] + ksb * 32);
        ldsm_x4(bf[1], offB[1] + ksb * 32);
        ldsm_x4(bf[2], offB[2] + ksb * 32);
        #pragma unroll
        for (int mf = 0; mf < 2; mf++)
            #pragma unroll
            for (int np = 0; np < 3; np++) {
                mma16816(acc[mf][np * 2 + 0], af[mf], &bf[np][0]);
                mma16816(acc[mf][np * 2 + 1], af[mf], &bf[np][2]);
            }
    }

    #pragma unroll
    for (int mf = 0; mf < 2; mf++) {
        #pragma unroll
        for (int h = 0; h < 2; h++) {
            int rl = warpM * 32 + mf * 16 + g + h * 8;
            if (rl < 98) {
                long tok = toks[rl];
                #pragma unroll
                for (int nf = 0; nf < 6; nf++) {
                    int col = warpN * 48 + nf * 8 + tig * 2;
                    float v0 = acc[mf][nf][h * 2 + 0] + bias[col];
                    float v1 = acc[mf][nf][h * 2 + 1] + bias[col + 1];
                    const float2 rr = *(const float2*)(x + tok * 96 + col);
                    v0 += rr.x; v1 += rr.y;
                    *(float2*)(x1 + tok * 96 + col) = make_float2(v0, v1);
                    *(__nv_bfloat162*)(x1b + tok * 96 + col) = __floats2bfloat162_rn(v0, v1);
                }
            }
        }
    }
}

// ---------------- fused 1x1-conv GEMM: GN+ReLU prologue, LN2 epilogue -------
__global__ __launch_bounds__(256)
void convp_kernel(const __nv_bfloat16* __restrict__ convb, const __nv_bfloat16* __restrict__ W,
                  const float* __restrict__ stats, const float* __restrict__ gnw,
                  const float* __restrict__ gnb, const float* __restrict__ x1,
                  const float* __restrict__ n2w, const float* __restrict__ n2b,
                  float* __restrict__ x2, __nv_bfloat16* __restrict__ xnb) {
    constexpr int PITCH = 104;
    __shared__ __align__(16) __nv_bfloat16 As[128 * PITCH];
    __shared__ __align__(16) __nv_bfloat16 Bs[96 * PITCH];
    __shared__ float redS[128][2], redQ[128][2];
    const int tid = threadIdx.x;
    const int wid = tid >> 5, lane = tid & 31;
    const int warpM = wid & 3, warpN = wid >> 2;
    const long row0 = (long)blockIdx.x * 128;

    const int bidx = (int)(row0 / 50176) * 4;
    for (int idx = tid; idx < 128 * 12; idx += 256) {
        int r = idx / 12, k8 = (idx % 12) * 8;
        uint4 cv = *(const uint4*)(convb + (row0 + r) * 96 + k8);
        const __nv_bfloat16* cp = (const __nv_bfloat16*)&cv;
        int gi = bidx + k8 / 24;
        float mu = stats[gi * 2], rs = stats[gi * 2 + 1];
        #pragma unroll
        for (int j = 0; j < 8; j += 2) {
            int c = k8 + j;
            float f0 = fmaxf((__bfloat162float(cp[j])     - mu) * rs * gnw[c]     + gnb[c],     0.f);
            float f1 = fmaxf((__bfloat162float(cp[j + 1]) - mu) * rs * gnw[c + 1] + gnb[c + 1], 0.f);
            *(__nv_bfloat162*)(&As[r * PITCH + c]) = __floats2bfloat162_rn(f0, f1);
        }
    }
    for (int idx = tid; idx < 96 * 12; idx += 256) {
        int n = idx / 12, k = (idx % 12) * 8;
        uint4 v = *(const uint4*)(W + n * 96 + k);
        *(uint4*)(&Bs[n * PITCH + k]) = v;
    }
    __syncthreads();

    float acc[2][6][4];
    #pragma unroll
    for (int i = 0; i < 2; i++)
        #pragma unroll
        for (int j = 0; j < 6; j++)
            #pragma unroll
            for (int q = 0; q < 4; q++) acc[i][j][q] = 0.f;

    const uint32_t smA = smem_u32(As), smB = smem_u32(Bs);
    const int t8 = lane & 7, tq = lane >> 3;
    const int rowA_base = warpM * 32 + t8 + (tq & 1) * 8;
    const int koffA = (tq >> 1) * 8;
    uint32_t offA[2];
    #pragma unroll
    for (int mf = 0; mf < 2; mf++)
        offA[mf] = smA + (uint32_t)(((rowA_base + mf * 16) * PITCH + koffA) * 2);
    const int rowB_base = warpN * 48 + t8 + (tq >> 1) * 8;
    const int koffB = (tq & 1) * 8;
    uint32_t offB[3];
    #pragma unroll
    for (int np = 0; np < 3; np++)
        offB[np] = smB + (uint32_t)(((rowB_base + np * 16) * PITCH + koffB) * 2);

    #pragma unroll
    for (int ks = 0; ks < 6; ks++) {
        uint32_t af[2][4], bf[3][4];
        ldsm_x4(af[0], offA[0] + ks * 32);
        ldsm_x4(af[1], offA[1] + ks * 32);
        ldsm_x4(bf[0], offB[0] + ks * 32);
        ldsm_x4(bf[1], offB[1] + ks * 32);
        ldsm_x4(bf[2], offB[2] + ks * 32);
        #pragma unroll
        for (int mf = 0; mf < 2; mf++)
            #pragma unroll
            for (int np = 0; np < 3; np++) {
                mma16816(acc[mf][np * 2 + 0], af[mf], &bf[np][0]);
                mma16816(acc[mf][np * 2 + 1], af[mf], &bf[np][2]);
            }
    }

    const int g = lane >> 2, tig = lane & 3;
    #pragma unroll
    for (int mf = 0; mf < 2; mf++)
        #pragma unroll
        for (int h = 0; h < 2; h++) {
            int rl = warpM * 32 + mf * 16 + g + h * 8;
            long row = row0 + rl;
            float s = 0.f, q2 = 0.f;
            #pragma unroll
            for (int nf = 0; nf < 6; nf++) {
                int col = warpN * 48 + nf * 8 + tig * 2;
                const float2 rr = *(const float2*)(x1 + row * 96 + col);
                float v0 = acc[mf][nf][h * 2 + 0] + rr.x;
                float v1 = acc[mf][nf][h * 2 + 1] + rr.y;
                acc[mf][nf][h * 2 + 0] = v0;
                acc[mf][nf][h * 2 + 1] = v1;
                s += v0 + v1; q2 += v0 * v0 + v1 * v1;
            }
            s  += __shfl_xor_sync(0xFFFFFFFFu, s, 1);
            q2 += __shfl_xor_sync(0xFFFFFFFFu, q2, 1);
            s  += __shfl_xor_sync(0xFFFFFFFFu, s, 2);
            q2 += __shfl_xor_sync(0xFFFFFFFFu, q2, 2);
            if (tig == 0) { redS[rl][warpN] = s; redQ[rl][warpN] = q2; }
        }
    __syncthreads();

    #pragma unroll
    for (int mf = 0; mf < 2; mf++)
        #pragma unroll
        for (int h = 0; h < 2; h++) {
            int rl = warpM * 32 + mf * 16 + g + h * 8;
            long row = row0 + rl;
            float tot = redS[rl][0] + redS[rl][1];
            float tq2 = redQ[rl][0] + redQ[rl][1];
            float mu = tot * (1.f / 96.f);
            float var = tq2 * (1.f / 96.f) - mu * mu;
            float rs = rsqrtf(var + 1e-5f);
            #pragma unroll
            for (int nf = 0; nf < 6; nf++) {
                int col = warpN * 48 + nf * 8 + tig * 2;
                float v0 = acc[mf][nf][h * 2 + 0];
                float v1 = acc[mf][nf][h * 2 + 1];
                *(float2*)(x2 + row * 96 + col) = make_float2(v0, v1);
                float n0 = (v0 - mu) * rs * n2w[col]     + n2b[col];
                float n1 = (v1 - mu) * rs * n2w[col + 1] + n2b[col + 1];
                *(__nv_bfloat162*)(xnb + row * 96 + col) = __floats2bfloat162_rn(n0, n1);
            }
        }
}

// ---------------- fused MLP: out = x2 + gelu(xn@W1^T+b1) @ W2^T + b2 --------
__global__ __launch_bounds__(256, 2)
void fc12_kernel(const __nv_bfloat16* __restrict__ xnb, const __nv_bfloat16* __restrict__ w1,
                 const __nv_bfloat16* __restrict__ w2, const float* __restrict__ b1,
                 const float* __restrict__ b2, const float* __restrict__ x2,
                 float* __restrict__ out) {
    constexpr int PITCH = 104;
    extern __shared__ __align__(16) char sm[];
    __nv_bfloat16* As  = (__nv_bfloat16*)sm;
    __nv_bfloat16* Bs1 = (__nv_bfloat16*)(sm + 26624);
    __nv_bfloat16* Bs2 = (__nv_bfloat16*)(sm + 46592);
    __nv_bfloat16* Hs  = (__nv_bfloat16*)(sm + 66560);
    const int tid = threadIdx.x;
    const int wid = tid >> 5, lane = tid & 31;
    const int warpM = wid & 3, warpN = wid >> 2;
    const long row0 = (long)blockIdx.x * 128;

    #pragma unroll
    for (int it = 0; it < 6; it++) {
        int idx = tid + it * 256;
        int r = idx / 12, k = (idx % 12) * 8;
        uint4 v = *(const uint4*)(xnb + (row0 + r) * 96 + k);
        *(uint4*)(&As[r * PITCH + k]) = v;
    }

    const uint32_t smA = smem_u32(As), smB1 = smem_u32(Bs1), smB2 = smem_u32(Bs2), smH = smem_u32(Hs);
    const int t8 = lane & 7, tq = lane >> 3;
    const int rowA_base = warpM * 32 + t8 + (tq & 1) * 8;
    const int koffA = (tq >> 1) * 8;
    uint32_t offA[2], offH[2];
    #pragma unroll
    for (int mf = 0; mf < 2; mf++) {
        offA[mf] = smA + (uint32_t)(((rowA_base + mf * 16) * PITCH + koffA) * 2);
        offH[mf] = smH + (uint32_t)(((rowA_base + mf * 16) * PITCH + koffA) * 2);
    }
    const int rowB_base = warpN * 48 + t8 + (tq >> 1) * 8;
    const int koffB = (tq & 1) * 8;
    uint32_t offB1[3], offB2[3];
    #pragma unroll
    for (int np = 0; np < 3; np++) {
        offB1[np] = smB1 + (uint32_t)(((rowB_base + np * 16) * PITCH + koffB) * 2);
        offB2[np] = smB2 + (uint32_t)(((rowB_base + np * 16) * PITCH + koffB) * 2);
    }
    const int g = lane >> 2, tig = lane & 3;

    float acc2[2][6][4];
    #pragma unroll
    for (int i = 0; i < 2; i++)
        #pragma unroll
        for (int j = 0; j < 6; j++)
            #pragma unroll
            for (int q = 0; q < 4; q++) acc2[i][j][q] = 0.f;

    for (int nc = 0; nc < 4; nc++) {
        __syncthreads();
        for (int idx = tid; idx < 96 * 12; idx += 256) {
            int n = idx / 12, k = (idx % 12) * 8;
            uint4 v1 = *(const uint4*)(w1 + (long)(nc * 96 + n) * 96 + k);
            *(uint4*)(&Bs1[n * PITCH + k]) = v1;
            uint4 v2 = *(const uint4*)(w2 + (long)n * 384 + nc * 96 + k);
            *(uint4*)(&Bs2[n * PITCH + k]) = v2;
        }
        __syncthreads();

        float acc1[2][6][4];
        #pragma unroll
        for (int i = 0; i < 2; i++)
            #pragma unroll
            for (int j = 0; j < 6; j++)
                #pragma unroll
                for (int q = 0; q < 4; q++) acc1[i][j][q] = 0.f;
        #pragma unroll
        for (int ks = 0; ks < 6; ks++) {
            uint32_t af[2][4], bf[3][4];
            ldsm_x4(af[0], offA[0] + ks * 32);
            ldsm_x4(af[1], offA[1] + ks * 32);
            ldsm_x4(bf[0], offB1[0] + ks * 32);
            ldsm_x4(bf[1], offB1[1] + ks * 32);
            ldsm_x4(bf[2], offB1[2] + ks * 32);
            #pragma unroll
            for (int mf = 0; mf < 2; mf++)
                #pragma unroll
                for (int np = 0; np < 3; np++) {
                    mma16816(acc1[mf][np * 2 + 0], af[mf], &bf[np][0]);
                    mma16816(acc1[mf][np * 2 + 1], af[mf], &bf[np][2]);
                }
        }
        #pragma unroll
        for (int mf = 0; mf < 2; mf++)
            #pragma unroll
            for (int nf = 0; nf < 6; nf++) {
                int hcol = warpN * 48 + nf * 8 + tig * 2;
                float bb0 = b1[nc * 96 + hcol], bb1 = b1[nc * 96 + hcol + 1];
                #pragma unroll
                for (int h = 0; h < 2; h++) {
                    int rl = warpM * 32 + mf * 16 + g + h * 8;
                    float v0 = gelu_exact(acc1[mf][nf][h * 2 + 0] + bb0);
                    float v1 = gelu_exact(acc1[mf][nf][h * 2 + 1] + bb1);
                    *(__nv_bfloat162*)(&Hs[rl * PITCH + hcol]) = __floats2bfloat162_rn(v0, v1);
                }
            }
        __syncthreads();

        #pragma unroll
        for (int ks = 0; ks < 6; ks++) {
            uint32_t af[2][4], bf[3][4];
            ldsm_x4(af[0], offH[0] + ks * 32);
            ldsm_x4(af[1], offH[1] + ks * 32);
            ldsm_x4(bf[0], offB2[0] + ks * 32);
            ldsm_x4(bf[1], offB2[1] + ks * 32);
            ldsm_x4(bf[2], offB2[2] + ks * 32);
            #pragma unroll
            for (int mf = 0; mf < 2; mf++)
                #pragma unroll
                for (int np = 0; np < 3; np++) {
                    mma16816(acc2[mf][np * 2 + 0], af[mf], &bf[np][0]);
                    mma16816(acc2[mf][np * 2 + 1], af[mf], &bf[np][2]);
                }
        }
    }

    #pragma unroll
    for (int mf = 0; mf < 2; mf++)
        #pragma unroll
        for (int nf = 0; nf < 6; nf++) {
            int col = warpN * 48 + nf * 8 + tig * 2;
            #pragma unroll
            for (int h = 0; h < 2; h++) {
                long row = row0 + warpM * 32 + mf * 16 + g + h * 8;
                const float2 rr = *(const float2*)(x2 + row * 96 + col);
                float v0 = acc2[mf][nf][h * 2 + 0] + b2[col]     + rr.x;
                float v1 = acc2[mf][nf][h * 2 + 1] + b2[col + 1] + rr.y;
                *(float2*)(out + row * 96 + col) = make_float2(v0, v1);
            }
        }
}

// ---------------- tensor-core grouped 3x3x3 conv + fused GN partials --------
#define CVP 40
#define WP3 872
__global__ __launch_bounds__(128)
void conv3t_kernel(const __nv_bfloat16* __restrict__ x, const __nv_bfloat16* __restrict__ wc3,
                   __nv_bfloat16* __restrict__ o, float* __restrict__ part2) {
    extern __shared__ __align__(16) char smc[];
    __nv_bfloat16* ws   = (__nv_bfloat16*)smc;
    __nv_bfloat16* in_s = (__nv_bfloat16*)(smc + 32 * WP3 * 2);
    __shared__ float redg[4][128];
    int bid = blockIdx.x;
    int g = bid % 3; int t = bid / 3;
    int tw = t % 7, th = (t / 7) % 7, b = t / 49;
    int h0 = th * 8, w0 = tw * 8;
    int tid = threadIdx.x, wrp = tid >> 5, lane = tid & 31;

    for (int idx = tid; idx < 32 * 108; idx += 128) {
        int row = idx / 108, kc = (idx % 108) * 8;
        uint4 v = *(const uint4*)(wc3 + (g * 32 + row) * 864 + kc);
        *(uint4*)(ws + row * WP3 + kc) = v;
    }

    auto load_plane = [&](int dde, int slot) {
        for (int idx = tid; idx < 400; idx += 128) {
            int pos = idx >> 2, c8 = (idx & 3) * 8;
            int hh = pos / 10, ww2 = pos % 10;
            int ih = h0 - 1 + hh, iw = w0 - 1 + ww2;
            uint4 v = make_uint4(0, 0, 0, 0);
            if (dde >= 0 && dde < 16 && ih >= 0 && ih < 56 && iw >= 0 && iw < 56)
                v = *(const uint4*)(x + ((long)((b * 16 + dde) * 56 + ih) * 56 + iw) * 96 + g * 32 + c8);
            *(uint4*)(in_s + slot * 4000 + (hh * 10 + ww2) * CVP + c8) = v;
        }
    };
    load_plane(-1, 2);
    load_plane(0,  0);

    const int t8 = lane & 7, tq = lane >> 3;
    const int mrow = t8 + (tq & 1) * 8;
    const int p = wrp * 16 + mrow;
    const int hr = p >> 3, wc = p & 7;
    const int koffA = (tq >> 1) * 8;
    const uint32_t inb = smem_u32(in_s);
    const uint32_t aoff = inb + (uint32_t)(((hr * 10 + wc) * CVP + koffA) * 2);
    const int nr = t8 + (tq >> 1) * 8;
    const int koffB = (tq & 1) * 8;
    const uint32_t wsb = smem_u32(ws);
    const uint32_t boff0 = wsb + (uint32_t)((nr * WP3 + koffB) * 2);
    const uint32_t boff1 = wsb + (uint32_t)(((nr + 16) * WP3 + koffB) * 2);
    const int g2 = lane >> 2, tig = lane & 3;
    const int nf_thresh = 3 - g;

    float gnS[2] = {0.f, 0.f}, gnQ[2] = {0.f, 0.f};

    for (int dcur = 0; dcur < 16; dcur++) {
        __syncthreads();
        load_plane(dcur + 1, (dcur + 1) % 3);
        __syncthreads();

        int slots[3] = { (dcur + 2) % 3, dcur % 3, (dcur + 1) % 3 };

        float acc[4][4];
        #pragma unroll
        for (int i = 0; i < 4; i++)
            #pragma unroll
            for (int q = 0; q < 4; q++) acc[i][q] = 0.f;

        #pragma unroll
        for (int kd = 0; kd < 3; kd++)
            #pragma unroll
            for (int kh = 0; kh < 3; kh++)
                #pragma unroll
                for (int kw = 0; kw < 3; kw++) {
                    uint32_t abase = aoff + (uint32_t)((slots[kd] * 4000 + (kh * 10 + kw) * CVP) * 2);
                    int tap = kd * 9 + kh * 3 + kw;
                    #pragma unroll
                    for (int s = 0; s < 2; s++) {
                        uint32_t af[4], b0[4], b1[4];
                        ldsm_x4(af, abase + s * 32);
                        ldsm_x4(b0, boff0 + (uint32_t)((tap * 32 + s * 16) * 2));
                        ldsm_x4(b1, boff1 + (uint32_t)((tap * 32 + s * 16) * 2));
                        mma16816(acc[0], af, &b0[0]);
                        mma16816(acc[1], af, &b0[2]);
                        mma16816(acc[2], af, &b1[0]);
                        mma16816(acc[3], af, &b1[2]);
                    }
                }

        #pragma unroll
        for (int hbit = 0; hbit < 2; hbit++) {
            long tok = ((long)(b * 16 + dcur) * 56 + (h0 + 2 * wrp + hbit)) * 56 + (w0 + g2);
            __nv_bfloat16* orow = o + tok * 96 + g * 32;
            #pragma unroll
            for (int nf = 0; nf < 4; nf++) {
                int co = nf * 8 + tig * 2;
                float v0 = acc[nf][hbit * 2], v1 = acc[nf][hbit * 2 + 1];
                *(__nv_bfloat162*)(orow + co) = __floats2bfloat162_rn(v0, v1);
                int bkt = (nf >= nf_thresh) ? 1 : 0;
                gnS[bkt] += v0 + v1;
                gnQ[bkt] += v0 * v0 + v1 * v1;
            }
        }
    }

    redg[0][tid] = gnS[0]; redg[1][tid] = gnQ[0];
    redg[2][tid] = gnS[1]; redg[3][tid] = gnQ[1];
    __syncthreads();
    for (int off = 64; off; off >>= 1) {
        if (tid < off) {
            #pragma unroll
            for (int j = 0; j < 4; j++) redg[j][tid] += redg[j][tid + off];
        }
        __syncthreads();
    }
    if (tid == 0) {
        part2[bid * 4 + 0] = redg[0][0];
        part2[bid * 4 + 1] = redg[1][0];
        part2[bid * 4 + 2] = redg[2][0];
        part2[bid * 4 + 3] = redg[3][0];
    }
}

// ---------------- GN stats combine (deterministic, from conv partials) ------
__global__ void gncomb_kernel(const float* __restrict__ part2, float* __restrict__ stats) {
    int t = threadIdx.x;
    if (t < 16) {
        int b = t >> 2, gi = t & 3;
        int gA = -1, kA = 0, gB = -1, kB = 0;
        if (gi == 0) { gA = 0; kA = 0; }
        else if (gi == 1) { gA = 0; kA = 1; gB = 1; kB = 0; }
        else if (gi == 2) { gA = 1; kA = 1; gB = 2; kB = 0; }
        else { gA = 2; kA = 1; }
        double s = 0.0, q2 = 0.0;
        for (int tile = 0; tile < 49; tile++) {
            int base = ((b * 49 + tile) * 3 + gA) * 4 + kA * 2;
            s += (double)part2[base]; q2 += (double)part2[base + 1];
        }
        if (gB >= 0) {
            for (int tile = 0; tile < 49; tile++) {
                int base = ((b * 49 + tile) * 3 + gB) * 4 + kB * 2;
                s += (double)part2[base]; q2 += (double)part2[base + 1];
            }
        }
        double N = 24.0 * 50176.0;
        double mu  = s / N;
        double var = q2 / N - mu * mu;
        stats[t * 2]     = (float)mu;
        stats[t * 2 + 1] = (float)(1.0 / sqrt(var + 1e-5));
    }
}

// ---------------- merged weight prep ----------------------------------------
__global__ void prep_kernel(const float* __restrict__ qkv_w, const float* __restrict__ proj_w,
                            const float* __restrict__ convp_w, const float* __restrict__ fc1_w,
                            const float* __restrict__ fc2_w, const float* __restrict__ conv3_w,
                            __nv_bfloat16* wq, __nv_bfloat16* wp, __nv_bfloat16* wc,
                            __nv_bfloat16* w1, __nv_bfloat16* w2, __nv_bfloat16* wc3) {
    int i = blockIdx.x * 256 + threadIdx.x;
    if (i < 27648) { wq[i] = __float2bfloat16(qkv_w[i]); return; }
    i -= 27648;
    if (i < 9216)  { wp[i] = __float2bfloat16(proj_w[i]); return; }
    i -= 9216;
    if (i < 9216)  { wc[i] = __float2bfloat16(convp_w[i]); return; }
    i -= 9216;
    if (i < 36864) { w1[i] = __float2bfloat16(fc1_w[i]); return; }
    i -= 36864;
    if (i < 36864) { w2[i] = __float2bfloat16(fc2_w[i]); return; }
    i -= 36864;
    if (i < 82944) {
        int co = i / 864, r = i % 864;
        int tap = r >> 5, ci = r & 31;
        wc3[i] = __float2bfloat16(conv3_w[co * 864 + ci * 27 + tap]);
    }
}

// ---------------- driver -----------------------------------------------------
extern "C" void kernel_launch(void* const* d_in, const int* in_sizes, int n_in,
                              void* d_out, int out_size) {
    const float* x       = (const float*)d_in[0];
    const float* n1w     = (const float*)d_in[1];
    const float* n1b     = (const float*)d_in[2];
    const float* qkv_w   = (const float*)d_in[3];
    const float* proj_w  = (const float*)d_in[4];
    const float* proj_b  = (const float*)d_in[5];
    const float* conv3_w = (const float*)d_in[6];
    const float* gn_w    = (const float*)d_in[7];
    const float* gn_b    = (const float*)d_in[8];
    const float* convp_w = (const float*)d_in[9];
    const float* n2w     = (const float*)d_in[10];
    const float* n2b     = (const float*)d_in[11];
    const float* fc1_w   = (const float*)d_in[12];
    const float* fc1_b   = (const float*)d_in[13];
    const float* fc2_w   = (const float*)d_in[14];
    const float* fc2_b   = (const float*)d_in[15];
    float* out = (float*)d_out;

    float *p_x1, *p_x2, *p_part2, *p_stats;
    __nv_bfloat16 *p_convb, *p_qkvb, *p_xnb, *p_x1b;
    __nv_bfloat16 *p_wq, *p_wp, *p_wc, *p_w1, *p_w2, *p_wc3;
    cudaGetSymbolAddress((void**)&p_x1,   g_x1);
    cudaGetSymbolAddress((void**)&p_x2,   g_x2);
    cudaGetSymbolAddress((void**)&p_part2,g_part2);
    cudaGetSymbolAddress((void**)&p_stats,g_stats);
    cudaGetSymbolAddress((void**)&p_convb,g_convb);
    cudaGetSymbolAddress((void**)&p_qkvb, g_qkvb);
    cudaGetSymbolAddress((void**)&p_xnb,  g_xnb);
    cudaGetSymbolAddress((void**)&p_x1b,  g_x1b);
    cudaGetSymbolAddress((void**)&p_wq,   g_wq);
    cudaGetSymbolAddress((void**)&p_wp,   g_wp);
    cudaGetSymbolAddress((void**)&p_wc,   g_wc);
    cudaGetSymbolAddress((void**)&p_w1,   g_w1);
    cudaGetSymbolAddress((void**)&p_w2,   g_w2);
    cudaGetSymbolAddress((void**)&p_wc3,  g_wc3);

    const int CONV_SMEM = 32 * WP3 * 2 + 3 * 4000 * 2;   // 79808
    const int FC_SMEM   = 26624 + 19968 + 19968 + 26624; // 93184
    const int AP_SMEM   = 26624 + 19968 + 18816 + 18816; // 84224
    cudaFuncSetAttribute(conv3t_kernel,  cudaFuncAttributeMaxDynamicSharedMemorySize, CONV_SMEM);
    cudaFuncSetAttribute(fc12_kernel,    cudaFuncAttributeMaxDynamicSharedMemorySize, FC_SMEM);
    cudaFuncSetAttribute(attnproj_kernel,cudaFuncAttributeMaxDynamicSharedMemorySize, AP_SMEM);

    // 0) merged weight prep
    prep_kernel<<<(202752 + 255) / 256, 256>>>(qkv_w, proj_w, convp_w, fc1_w, fc2_w, conv3_w,
                                               p_wq, p_wp, p_wc, p_w1, p_w2, p_wc3);
    // 1) qkv = LN1(x) @ qkv_w^T -> bf16
    tgemm<3,4,1><<<1568, 256>>>(x, p_wq, nullptr, nullptr, p_qkvb, nullptr, n1w, n1b);
    // 2) fused attention + proj: x1 = x + attn(qkv) @ wp^T + proj_b
    attnproj_kernel<<<2048, 256, AP_SMEM>>>(p_qkvb, p_wp, proj_b, x, p_x1, p_x1b);
    // 3) grouped conv (tensor cores, full depth, fused GN partials, bf16 out)
    conv3t_kernel<<<588, 128, CONV_SMEM>>>(p_x1b, p_wc3, p_convb, p_part2);
    // 4) GN stats combine (deterministic)
    gncomb_kernel<<<1, 16>>>(p_part2, p_stats);
    // 5) fused: x2 = x1 + relu(GN(conv)) @ convp^T ; xnb = LN2(x2)
    convp_kernel<<<1568, 256>>>(p_convb, p_wc, p_stats, gn_w, gn_b, p_x1, n2w, n2b, p_x2, p_xnb);
    // 6) fused MLP
    fc12_kernel<<<1568, 256, FC_SMEM>>>(p_xnb, p_w1, p_w2, fc1_b, fc2_b, p_x2, out);
}

// round 13
// speedup vs baseline: 1.4509x; 1.4509x over previous
#include <cuda_runtime.h>
#include <cuda_bf16.h>
#include <math.h>
#include <cstdint>

// ---------------- problem constants ----------------
#define NTOK 200704           // 4*16*56*56

// ---------------- scratch (static device globals; allowed) ----------------
__device__ __align__(16) float g_x1  [NTOK*96];
__device__ __align__(16) float g_x2  [NTOK*96];
__device__ __align__(16) float g_part2[588*4];
__device__ __align__(16) float g_stats[16*2];
__device__ __align__(16) __nv_bfloat16 g_convb[NTOK*96];
__device__ __align__(16) __nv_bfloat16 g_qkvb[NTOK*288];
__device__ __align__(16) __nv_bfloat16 g_xnb [NTOK*96];
__device__ __align__(16) __nv_bfloat16 g_attb[NTOK*96];
__device__ __align__(16) __nv_bfloat16 g_x1b [NTOK*96];
__device__ __align__(16) __nv_bfloat16 g_wq  [288*96];
__device__ __align__(16) __nv_bfloat16 g_wp  [96*96];
__device__ __align__(16) __nv_bfloat16 g_wc  [96*96];
__device__ __align__(16) __nv_bfloat16 g_w1  [384*96];
__device__ __align__(16) __nv_bfloat16 g_w2  [96*384];
__device__ __align__(16) __nv_bfloat16 g_wc3 [96*864];

// ---------------- warp-MMA helpers ------------------------------------------
__device__ __forceinline__ uint32_t smem_u32(const void* p) {
    uint32_t a;
    asm("{ .reg .u64 t; cvta.to.shared.u64 t, %1; cvt.u32.u64 %0, t; }" : "=r"(a) : "l"(p));
    return a;
}
__device__ __forceinline__ void ldsm_x4(uint32_t* r, uint32_t addr) {
    asm volatile("ldmatrix.sync.aligned.m8n8.x4.shared.b16 {%0,%1,%2,%3}, [%4];"
        : "=r"(r[0]), "=r"(r[1]), "=r"(r[2]), "=r"(r[3]) : "r"(addr));
}
__device__ __forceinline__ void mma16816(float* d, const uint32_t* a, const uint32_t* b) {
    asm volatile(
        "mma.sync.aligned.m16n8k16.row.col.f32.bf16.bf16.f32 "
        "{%0,%1,%2,%3}, {%4,%5,%6,%7}, {%8,%9}, {%0,%1,%2,%3};"
        : "+f"(d[0]), "+f"(d[1]), "+f"(d[2]), "+f"(d[3])
        : "r"(a[0]), "r"(a[1]), "r"(a[2]), "r"(a[3]), "r"(b[0]), "r"(b[1]));
}
__device__ __forceinline__ float gelu_exact(float v) {
    return 0.5f * v * (1.f + erff(v * 0.70710678118654752f));
}

// ---------------- tensor-core GEMM (K=96), M-tile 128 -----------------------
// PROLOG 0: A bf16 load. PROLOG 1: A fp32 + fused LayerNorm -> bf16.
// EPI: 3 = +bias+resid fp32 AND bf16 copy; 4 = bf16 store.
template<int NCH, int EPI, int PROLOG>
__global__ __launch_bounds__(256)
void tgemm(const void* __restrict__ Ax, const __nv_bfloat16* __restrict__ W,
           const float* __restrict__ bias, const float* __restrict__ resid,
           void* __restrict__ outv, __nv_bfloat16* __restrict__ out2,
           const float* __restrict__ lnw, const float* __restrict__ lnb) {
    constexpr int PITCH = 104;
    constexpr int NOtot = 96 * NCH;
    __shared__ __align__(16) __nv_bfloat16 As[128 * PITCH];
    __shared__ __align__(16) __nv_bfloat16 Bs[96 * PITCH];
    const int tid = threadIdx.x;
    const int wid = tid >> 5, lane = tid & 31;
    const int warpM = wid & 3, warpN = wid >> 2;
    const long row0 = (long)blockIdx.x * 128;

    if (PROLOG == 0) {
        const __nv_bfloat16* A = (const __nv_bfloat16*)Ax;
        #pragma unroll
        for (int it = 0; it < 6; it++) {
            int idx = tid + it * 256;
            int r = idx / 12, k = (idx % 12) * 8;
            uint4 v = *(const uint4*)(A + (row0 + r) * 96 + k);
            *(uint4*)(&As[r * PITCH + k]) = v;
        }
    } else {
        const int r = tid >> 1, half = tid & 1;
        const float* xr = (const float*)Ax + (row0 + r) * 96 + half * 48;
        float vb[48];
        float s = 0.f, q2 = 0.f;
        #pragma unroll
        for (int i = 0; i < 12; i++) {
            float4 f = *(const float4*)(xr + i * 4);
            vb[i*4] = f.x; vb[i*4+1] = f.y; vb[i*4+2] = f.z; vb[i*4+3] = f.w;
            s  += f.x + f.y + f.z + f.w;
            q2 += f.x*f.x + f.y*f.y + f.z*f.z + f.w*f.w;
        }
        s  += __shfl_xor_sync(0xFFFFFFFFu, s, 1);
        q2 += __shfl_xor_sync(0xFFFFFFFFu, q2, 1);
        float mu = s * (1.f / 96.f);
        float var = q2 * (1.f / 96.f) - mu * mu;
        float rs = rsqrtf(var + 1e-5f);
        #pragma unroll
        for (int j = 0; j < 48; j += 2) {
            int c = half * 48 + j;
            float n0 = (vb[j]   - mu) * rs * lnw[c]     + lnb[c];
            float n1 = (vb[j+1] - mu) * rs * lnw[c + 1] + lnb[c + 1];
            *(__nv_bfloat162*)(&As[r * PITCH + c]) = __floats2bfloat162_rn(n0, n1);
        }
    }

    const uint32_t smA = smem_u32(As), smB = smem_u32(Bs);
    const int t8 = lane & 7, tq = lane >> 3;
    const int rowA_base = warpM * 32 + t8 + (tq & 1) * 8;
    const int koffA = (tq >> 1) * 8;
    uint32_t offA[2];
    #pragma unroll
    for (int mf = 0; mf < 2; mf++)
        offA[mf] = smA + (uint32_t)(((rowA_base + mf * 16) * PITCH + koffA) * 2);
    const int rowB_base = warpN * 48 + t8 + (tq >> 1) * 8;
    const int koffB = (tq & 1) * 8;
    uint32_t offB[3];
    #pragma unroll
    for (int np = 0; np < 3; np++)
        offB[np] = smB + (uint32_t)(((rowB_base + np * 16) * PITCH + koffB) * 2);
    const int g = lane >> 2, tig = lane & 3;

    #pragma unroll
    for (int nc = 0; nc < NCH; nc++) {
        const int col0 = nc * 96;
        if (nc) __syncthreads();
        for (int idx = tid; idx < 96 * 12; idx += 256) {
            int n = idx / 12, k = (idx % 12) * 8;
            uint4 v = *(const uint4*)(W + (long)(col0 + n) * 96 + k);
            *(uint4*)(&Bs[n * PITCH + k]) = v;
        }
        __syncthreads();

        float acc[2][6][4];
        #pragma unroll
        for (int i = 0; i < 2; i++)
            #pragma unroll
            for (int j = 0; j < 6; j++)
                #pragma unroll
                for (int q = 0; q < 4; q++) acc[i][j][q] = 0.f;
        #pragma unroll
        for (int ks = 0; ks < 6; ks++) {
            uint32_t af[2][4], bf[3][4];
            ldsm_x4(af[0], offA[0] + ks * 32);
            ldsm_x4(af[1], offA[1] + ks * 32);
            ldsm_x4(bf[0], offB[0] + ks * 32);
            ldsm_x4(bf[1], offB[1] + ks * 32);
            ldsm_x4(bf[2], offB[2] + ks * 32);
            #pragma unroll
            for (int mf = 0; mf < 2; mf++)
                #pragma unroll
                for (int np = 0; np < 3; np++) {
                    mma16816(acc[mf][np * 2 + 0], af[mf], &bf[np][0]);
                    mma16816(acc[mf][np * 2 + 1], af[mf], &bf[np][2]);
                }
        }

        #pragma unroll
        for (int mf = 0; mf < 2; mf++) {
            #pragma unroll
            for (int nf = 0; nf < 6; nf++) {
                int col = col0 + warpN * 48 + nf * 8 + tig * 2;
                #pragma unroll
                for (int h = 0; h < 2; h++) {
                    long row = row0 + warpM * 32 + mf * 16 + g + h * 8;
                    float v0 = acc[mf][nf][h * 2 + 0];
                    float v1 = acc[mf][nf][h * 2 + 1];
                    if (EPI == 3) {
                        if (bias) { v0 += bias[col]; v1 += bias[col + 1]; }
                        const float2 rr = *(const float2*)(resid + row * NOtot + col);
                        v0 += rr.x; v1 += rr.y;
                        *(float2*)((float*)outv + row * NOtot + col) = make_float2(v0, v1);
                        *(__nv_bfloat162*)(out2 + row * NOtot + col) = __floats2bfloat162_rn(v0, v1);
                    } else {
                        *(__nv_bfloat162*)((__nv_bfloat16*)outv + row * NOtot + col) = __floats2bfloat162_rn(v0, v1);
                    }
                }
            }
        }
    }
}

// ---------------- multi-dilate local attention (vectorized bf16) ------------
__global__ void attn_kernel(const __nv_bfloat16* __restrict__ qkv, __nv_bfloat16* __restrict__ outb) {
    __shared__ __align__(16) __nv_bfloat16 ks[98 * 32];
    __shared__ __align__(16) __nv_bfloat16 vs[98 * 32];
    __shared__ int toks[98];
    int win = blockIdx.x;
    int dil = blockIdx.y + 1;
    int choff = blockIdx.y * 32;
    int tid = threadIdx.x;
    if (tid < 98) {
        int b  = win >> 9;
        int dq = (win >> 6) & 7;
        int hq = (win >> 3) & 7;
        int wq = win & 7;
        int wd = tid / 49, rem = tid % 49;
        int wh = rem / 7, ww = rem % 7;
        int d = dq * 2 + wd, h = hq * 7 + wh, w = wq * 7 + ww;
        toks[tid] = ((b * 16 + d) * 56 + h) * 56 + w;
    }
    __syncthreads();
    for (int idx = tid; idx < 98 * 8; idx += 224) {
        int n = idx >> 3, sub = idx & 7;
        int isv = sub >> 2, c8 = (sub & 3) * 8;
        long base = (long)toks[n] * 288 + choff + (isv ? 192 : 96) + c8;
        uint4 v = *(const uint4*)(qkv + base);
        *(uint4*)((isv ? vs : ks) + n * 32 + c8) = v;
    }
    __syncthreads();
    if (tid < 196) {
        int n = tid >> 1, head = tid & 1;
        long qbase = (long)toks[n] * 288 + choff + head * 16;
        float q[16];
        {
            uint4 qa = *(const uint4*)(qkv + qbase);
            uint4 qb = *(const uint4*)(qkv + qbase + 8);
            const __nv_bfloat162* qp = (const __nv_bfloat162*)&qa;
            #pragma unroll
            for (int i = 0; i < 4; i++) {
                float2 f = __bfloat1622float2(qp[i]);
                q[i * 2] = f.x; q[i * 2 + 1] = f.y;
            }
            qp = (const __nv_bfloat162*)&qb;
            #pragma unroll
            for (int i = 0; i < 4; i++) {
                float2 f = __bfloat1622float2(qp[i]);
                q[8 + i * 2] = f.x; q[8 + i * 2 + 1] = f.y;
            }
        }
        float lr[3]; int mm[3];
        #pragma unroll
        for (int j = 0; j < 3; j++) {
            int m = n + (j - 1) * dil;
            mm[j] = m;
            float s = 0.f;
            if (m >= 0 && m < 98) {
                const __nv_bfloat162* kr = (const __nv_bfloat162*)&ks[m * 32 + head * 16];
                #pragma unroll
                for (int c = 0; c < 8; c++) {
                    float2 f = __bfloat1622float2(kr[c]);
                    s += q[c * 2] * f.x + q[c * 2 + 1] * f.y;
                }
            }
            lr[j] = s * 0.25f;
        }
        float mx = fmaxf(0.f, fmaxf(lr[0], fmaxf(lr[1], lr[2])));
        float e[3];
        e[0] = expf(lr[0] - mx); e[1] = expf(lr[1] - mx); e[2] = expf(lr[2] - mx);
        float denom = 6.f * expf(-mx) + e[0] + e[1] + e[2];
        float o[16];
        #pragma unroll
        for (int c = 0; c < 16; c++) o[c] = 0.f;
        #pragma unroll
        for (int j = 0; j < 3; j++) {
            int m = mm[j];
            if (m >= 0 && m < 98) {
                float a = e[j] / denom;
                const __nv_bfloat162* vr = (const __nv_bfloat162*)&vs[m * 32 + head * 16];
                #pragma unroll
                for (int c = 0; c < 8; c++) {
                    float2 f = __bfloat1622float2(vr[c]);
                    o[c * 2]     += a * f.x;
                    o[c * 2 + 1] += a * f.y;
                }
            }
        }
        long obase = (long)toks[n] * 96 + choff + head * 16;
        #pragma unroll
        for (int c = 0; c < 8; c++)
            *(__nv_bfloat162*)(outb + obase + c * 2) = __floats2bfloat162_rn(o[c * 2], o[c * 2 + 1]);
    }
}

// ---------------- fused 1x1-conv GEMM: GN+ReLU prologue, LN2 epilogue -------
__global__ __launch_bounds__(256)
void convp_kernel(const __nv_bfloat16* __restrict__ convb, const __nv_bfloat16* __restrict__ W,
                  const float* __restrict__ stats, const float* __restrict__ gnw,
                  const float* __restrict__ gnb, const float* __restrict__ x1,
                  const float* __restrict__ n2w, const float* __restrict__ n2b,
                  float* __restrict__ x2, __nv_bfloat16* __restrict__ xnb) {
    constexpr int PITCH = 104;
    __shared__ __align__(16) __nv_bfloat16 As[128 * PITCH];
    __shared__ __align__(16) __nv_bfloat16 Bs[96 * PITCH];
    __shared__ float redS[128][2], redQ[128][2];
    const int tid = threadIdx.x;
    const int wid = tid >> 5, lane = tid & 31;
    const int warpM = wid & 3, warpN = wid >> 2;
    const long row0 = (long)blockIdx.x * 128;

    const int bidx = (int)(row0 / 50176) * 4;
    for (int idx = tid; idx < 128 * 12; idx += 256) {
        int r = idx / 12, k8 = (idx % 12) * 8;
        uint4 cv = *(const uint4*)(convb + (row0 + r) * 96 + k8);
        const __nv_bfloat16* cp = (const __nv_bfloat16*)&cv;
        int gi = bidx + k8 / 24;
        float mu = stats[gi * 2], rs = stats[gi * 2 + 1];
        #pragma unroll
        for (int j = 0; j < 8; j += 2) {
            int c = k8 + j;
            float f0 = fmaxf((__bfloat162float(cp[j])     - mu) * rs * gnw[c]     + gnb[c],     0.f);
            float f1 = fmaxf((__bfloat162float(cp[j + 1]) - mu) * rs * gnw[c + 1] + gnb[c + 1], 0.f);
            *(__nv_bfloat162*)(&As[r * PITCH + c]) = __floats2bfloat162_rn(f0, f1);
        }
    }
    for (int idx = tid; idx < 96 * 12; idx += 256) {
        int n = idx / 12, k = (idx % 12) * 8;
        uint4 v = *(const uint4*)(W + n * 96 + k);
        *(uint4*)(&Bs[n * PITCH + k]) = v;
    }
    __syncthreads();

    float acc[2][6][4];
    #pragma unroll
    for (int i = 0; i < 2; i++)
        #pragma unroll
        for (int j = 0; j < 6; j++)
            #pragma unroll
            for (int q = 0; q < 4; q++) acc[i][j][q] = 0.f;

    const uint32_t smA = smem_u32(As), smB = smem_u32(Bs);
    const int t8 = lane & 7, tq = lane >> 3;
    const int rowA_base = warpM * 32 + t8 + (tq & 1) * 8;
    const int koffA = (tq >> 1) * 8;
    uint32_t offA[2];
    #pragma unroll
    for (int mf = 0; mf < 2; mf++)
        offA[mf] = smA + (uint32_t)(((rowA_base + mf * 16) * PITCH + koffA) * 2);
    const int rowB_base = warpN * 48 + t8 + (tq >> 1) * 8;
    const int koffB = (tq & 1) * 8;
    uint32_t offB[3];
    #pragma unroll
    for (int np = 0; np < 3; np++)
        offB[np] = smB + (uint32_t)(((rowB_base + np * 16) * PITCH + koffB) * 2);

    #pragma unroll
    for (int ks = 0; ks < 6; ks++) {
        uint32_t af[2][4], bf[3][4];
        ldsm_x4(af[0], offA[0] + ks * 32);
        ldsm_x4(af[1], offA[1] + ks * 32);
        ldsm_x4(bf[0], offB[0] + ks * 32);
        ldsm_x4(bf[1], offB[1] + ks * 32);
        ldsm_x4(bf[2], offB[2] + ks * 32);
        #pragma unroll
        for (int mf = 0; mf < 2; mf++)
            #pragma unroll
            for (int np = 0; np < 3; np++) {
                mma16816(acc[mf][np * 2 + 0], af[mf], &bf[np][0]);
                mma16816(acc[mf][np * 2 + 1], af[mf], &bf[np][2]);
            }
    }

    const int g = lane >> 2, tig = lane & 3;
    #pragma unroll
    for (int mf = 0; mf < 2; mf++)
        #pragma unroll
        for (int h = 0; h < 2; h++) {
            int rl = warpM * 32 + mf * 16 + g + h * 8;
            long row = row0 + rl;
            float s = 0.f, q2 = 0.f;
            #pragma unroll
            for (int nf = 0; nf < 6; nf++) {
                int col = warpN * 48 + nf * 8 + tig * 2;
                const float2 rr = *(const float2*)(x1 + row * 96 + col);
                float v0 = acc[mf][nf][h * 2 + 0] + rr.x;
                float v1 = acc[mf][nf][h * 2 + 1] + rr.y;
                acc[mf][nf][h * 2 + 0] = v0;
                acc[mf][nf][h * 2 + 1] = v1;
                s += v0 + v1; q2 += v0 * v0 + v1 * v1;
            }
            s  += __shfl_xor_sync(0xFFFFFFFFu, s, 1);
            q2 += __shfl_xor_sync(0xFFFFFFFFu, q2, 1);
            s  += __shfl_xor_sync(0xFFFFFFFFu, s, 2);
            q2 += __shfl_xor_sync(0xFFFFFFFFu, q2, 2);
            if (tig == 0) { redS[rl][warpN] = s; redQ[rl][warpN] = q2; }
        }
    __syncthreads();

    #pragma unroll
    for (int mf = 0; mf < 2; mf++)
        #pragma unroll
        for (int h = 0; h < 2; h++) {
            int rl = warpM * 32 + mf * 16 + g + h * 8;
            long row = row0 + rl;
            float tot = redS[rl][0] + redS[rl][1];
            float tq2 = redQ[rl][0] + redQ[rl][1];
            float mu = tot * (1.f / 96.f);
            float var = tq2 * (1.f / 96.f) - mu * mu;
            float rs = rsqrtf(var + 1e-5f);
            #pragma unroll
            for (int nf = 0; nf < 6; nf++) {
                int col = warpN * 48 + nf * 8 + tig * 2;
                float v0 = acc[mf][nf][h * 2 + 0];
                float v1 = acc[mf][nf][h * 2 + 1];
                *(float2*)(x2 + row * 96 + col) = make_float2(v0, v1);
                float n0 = (v0 - mu) * rs * n2w[col]     + n2b[col];
                float n1 = (v1 - mu) * rs * n2w[col + 1] + n2b[col + 1];
                *(__nv_bfloat162*)(xnb + row * 96 + col) = __floats2bfloat162_rn(n0, n1);
            }
        }
}

// ---------------- fused MLP: out = x2 + gelu(xn@W1^T+b1) @ W2^T + b2 --------
__global__ __launch_bounds__(256, 2)
void fc12_kernel(const __nv_bfloat16* __restrict__ xnb, const __nv_bfloat16* __restrict__ w1,
                 const __nv_bfloat16* __restrict__ w2, const float* __restrict__ b1,
                 const float* __restrict__ b2, const float* __restrict__ x2,
                 float* __restrict__ out) {
    constexpr int PITCH = 104;
    extern __shared__ __align__(16) char sm[];
    __nv_bfloat16* As  = (__nv_bfloat16*)sm;
    __nv_bfloat16* Bs1 = (__nv_bfloat16*)(sm + 26624);
    __nv_bfloat16* Bs2 = (__nv_bfloat16*)(sm + 46592);
    __nv_bfloat16* Hs  = (__nv_bfloat16*)(sm + 66560);
    const int tid = threadIdx.x;
    const int wid = tid >> 5, lane = tid & 31;
    const int warpM = wid & 3, warpN = wid >> 2;
    const long row0 = (long)blockIdx.x * 128;

    #pragma unroll
    for (int it = 0; it < 6; it++) {
        int idx = tid + it * 256;
        int r = idx / 12, k = (idx % 12) * 8;
        uint4 v = *(const uint4*)(xnb + (row0 + r) * 96 + k);
        *(uint4*)(&As[r * PITCH + k]) = v;
    }

    const uint32_t smA = smem_u32(As), smB1 = smem_u32(Bs1), smB2 = smem_u32(Bs2), smH = smem_u32(Hs);
    const int t8 = lane & 7, tq = lane >> 3;
    const int rowA_base = warpM * 32 + t8 + (tq & 1) * 8;
    const int koffA = (tq >> 1) * 8;
    uint32_t offA[2], offH[2];
    #pragma unroll
    for (int mf = 0; mf < 2; mf++) {
        offA[mf] = smA + (uint32_t)(((rowA_base + mf * 16) * PITCH + koffA) * 2);
        offH[mf] = smH + (uint32_t)(((rowA_base + mf * 16) * PITCH + koffA) * 2);
    }
    const int rowB_base = warpN * 48 + t8 + (tq >> 1) * 8;
    const int koffB = (tq & 1) * 8;
    uint32_t offB1[3], offB2[3];
    #pragma unroll
    for (int np = 0; np < 3; np++) {
        offB1[np] = smB1 + (uint32_t)(((rowB_base + np * 16) * PITCH + koffB) * 2);
        offB2[np] = smB2 + (uint32_t)(((rowB_base + np * 16) * PITCH + koffB) * 2);
    }
    const int g = lane >> 2, tig = lane & 3;

    float acc2[2][6][4];
    #pragma unroll
    for (int i = 0; i < 2; i++)
        #pragma unroll
        for (int j = 0; j < 6; j++)
            #pragma unroll
            for (int q = 0; q < 4; q++) acc2[i][j][q] = 0.f;

    for (int nc = 0; nc < 4; nc++) {
        __syncthreads();
        for (int idx = tid; idx < 96 * 12; idx += 256) {
            int n = idx / 12, k = (idx % 12) * 8;
            uint4 v1 = *(const uint4*)(w1 + (long)(nc * 96 + n) * 96 + k);
            *(uint4*)(&Bs1[n * PITCH + k]) = v1;
            uint4 v2 = *(const uint4*)(w2 + (long)n * 384 + nc * 96 + k);
            *(uint4*)(&Bs2[n * PITCH + k]) = v2;
        }
        __syncthreads();

        float acc1[2][6][4];
        #pragma unroll
        for (int i = 0; i < 2; i++)
            #pragma unroll
            for (int j = 0; j < 6; j++)
                #pragma unroll
                for (int q = 0; q < 4; q++) acc1[i][j][q] = 0.f;
        #pragma unroll
        for (int ks = 0; ks < 6; ks++) {
            uint32_t af[2][4], bf[3][4];
            ldsm_x4(af[0], offA[0] + ks * 32);
            ldsm_x4(af[1], offA[1] + ks * 32);
            ldsm_x4(bf[0], offB1[0] + ks * 32);
            ldsm_x4(bf[1], offB1[1] + ks * 32);
            ldsm_x4(bf[2], offB1[2] + ks * 32);
            #pragma unroll
            for (int mf = 0; mf < 2; mf++)
                #pragma unroll
                for (int np = 0; np < 3; np++) {
                    mma16816(acc1[mf][np * 2 + 0], af[mf], &bf[np][0]);
                    mma16816(acc1[mf][np * 2 + 1], af[mf], &bf[np][2]);
                }
        }
        #pragma unroll
        for (int mf = 0; mf < 2; mf++)
            #pragma unroll
            for (int nf = 0; nf < 6; nf++) {
                int hcol = warpN * 48 + nf * 8 + tig * 2;
                float bb0 = b1[nc * 96 + hcol], bb1 = b1[nc * 96 + hcol + 1];
                #pragma unroll
                for (int h = 0; h < 2; h++) {
                    int rl = warpM * 32 + mf * 16 + g + h * 8;
                    float v0 = gelu_exact(acc1[mf][nf][h * 2 + 0] + bb0);
                    float v1 = gelu_exact(acc1[mf][nf][h * 2 + 1] + bb1);
                    *(__nv_bfloat162*)(&Hs[rl * PITCH + hcol]) = __floats2bfloat162_rn(v0, v1);
                }
            }
        __syncthreads();

        #pragma unroll
        for (int ks = 0; ks < 6; ks++) {
            uint32_t af[2][4], bf[3][4];
            ldsm_x4(af[0], offH[0] + ks * 32);
            ldsm_x4(af[1], offH[1] + ks * 32);
            ldsm_x4(bf[0], offB2[0] + ks * 32);
            ldsm_x4(bf[1], offB2[1] + ks * 32);
            ldsm_x4(bf[2], offB2[2] + ks * 32);
            #pragma unroll
            for (int mf = 0; mf < 2; mf++)
                #pragma unroll
                for (int np = 0; np < 3; np++) {
                    mma16816(acc2[mf][np * 2 + 0], af[mf], &bf[np][0]);
                    mma16816(acc2[mf][np * 2 + 1], af[mf], &bf[np][2]);
                }
        }
    }

    #pragma unroll
    for (int mf = 0; mf < 2; mf++)
        #pragma unroll
        for (int nf = 0; nf < 6; nf++) {
            int col = warpN * 48 + nf * 8 + tig * 2;
            #pragma unroll
            for (int h = 0; h < 2; h++) {
                long row = row0 + warpM * 32 + mf * 16 + g + h * 8;
                const float2 rr = *(const float2*)(x2 + row * 96 + col);
                float v0 = acc2[mf][nf][h * 2 + 0] + b2[col]     + rr.x;
                float v1 = acc2[mf][nf][h * 2 + 1] + b2[col + 1] + rr.y;
                *(float2*)(out + row * 96 + col) = make_float2(v0, v1);
            }
        }
}

// ---------------- tensor-core grouped 3x3x3 conv (256 thr, co-split) --------
#define CVP 40
#define WP3 872
__global__ __launch_bounds__(256)
void conv3t_kernel(const __nv_bfloat16* __restrict__ x, const __nv_bfloat16* __restrict__ wc3,
                   __nv_bfloat16* __restrict__ o, float* __restrict__ part2) {
    extern __shared__ __align__(16) char smc[];
    __nv_bfloat16* ws   = (__nv_bfloat16*)smc;
    __nv_bfloat16* in_s = (__nv_bfloat16*)(smc + 32 * WP3 * 2);
    __shared__ float redg[4][256];
    int bid = blockIdx.x;
    int g = bid % 3; int t = bid / 3;
    int tw = t % 7, th = (t / 7) % 7, b = t / 49;
    int h0 = th * 8, w0 = tw * 8;
    int tid = threadIdx.x, wid = tid >> 5, lane = tid & 31;
    const int wrp2 = wid & 3;          // position group (rows 2*wrp2, 2*wrp2+1)
    const int ch   = wid >> 2;         // co half: 0 -> co 0..15, 1 -> co 16..31

    for (int idx = tid; idx < 32 * 108; idx += 256) {
        int row = idx / 108, kc = (idx % 108) * 8;
        uint4 v = *(const uint4*)(wc3 + (g * 32 + row) * 864 + kc);
        *(uint4*)(ws + row * WP3 + kc) = v;
    }

    auto load_plane = [&](int dde, int slot) {
        for (int idx = tid; idx < 400; idx += 256) {
            int pos = idx >> 2, c8 = (idx & 3) * 8;
            int hh = pos / 10, ww2 = pos % 10;
            int ih = h0 - 1 + hh, iw = w0 - 1 + ww2;
            uint4 v = make_uint4(0, 0, 0, 0);
            if (dde >= 0 && dde < 16 && ih >= 0 && ih < 56 && iw >= 0 && iw < 56)
                v = *(const uint4*)(x + ((long)((b * 16 + dde) * 56 + ih) * 56 + iw) * 96 + g * 32 + c8);
            *(uint4*)(in_s + slot * 4000 + (hh * 10 + ww2) * CVP + c8) = v;
        }
    };
    load_plane(-1, 2);
    load_plane(0,  0);

    const int t8 = lane & 7, tq = lane >> 3;
    const int mrow = t8 + (tq & 1) * 8;
    const int p = wrp2 * 16 + mrow;
    const int hr = p >> 3, wc = p & 7;
    const int koffA = (tq >> 1) * 8;
    const uint32_t inb = smem_u32(in_s);
    const uint32_t aoff = inb + (uint32_t)(((hr * 10 + wc) * CVP + koffA) * 2);
    const int nr = ch * 16 + t8 + (tq >> 1) * 8;
    const int koffB = (tq & 1) * 8;
    const uint32_t wsb = smem_u32(ws);
    const uint32_t boff = wsb + (uint32_t)((nr * WP3 + koffB) * 2);
    const int g2 = lane >> 2, tig = lane & 3;
    const int nf_thresh = 3 - g;        // GN split over global nf (0..3)

    float gnS[2] = {0.f, 0.f}, gnQ[2] = {0.f, 0.f};

    for (int dcur = 0; dcur < 16; dcur++) {
        __syncthreads();
        load_plane(dcur + 1, (dcur + 1) % 3);
        __syncthreads();

        int slots[3] = { (dcur + 2) % 3, dcur % 3, (dcur + 1) % 3 };

        float acc[2][4];
        #pragma unroll
        for (int i = 0; i < 2; i++)
            #pragma unroll
            for (int q = 0; q < 4; q++) acc[i][q] = 0.f;

        #pragma unroll
        for (int kd = 0; kd < 3; kd++)
            #pragma unroll
            for (int kh = 0; kh < 3; kh++)
                #pragma unroll
                for (int kw = 0; kw < 3; kw++) {
                    uint32_t abase = aoff + (uint32_t)((slots[kd] * 4000 + (kh * 10 + kw) * CVP) * 2);
                    int tap = kd * 9 + kh * 3 + kw;
                    #pragma unroll
                    for (int s = 0; s < 2; s++) {
                        uint32_t af[4], bfr[4];
                        ldsm_x4(af, abase + s * 32);
                        ldsm_x4(bfr, boff + (uint32_t)((tap * 32 + s * 16) * 2));
                        mma16816(acc[0], af, &bfr[0]);
                        mma16816(acc[1], af, &bfr[2]);
                    }
                }

        #pragma unroll
        for (int hbit = 0; hbit < 2; hbit++) {
            long tok = ((long)(b * 16 + dcur) * 56 + (h0 + 2 * wrp2 + hbit)) * 56 + (w0 + g2);
            __nv_bfloat16* orow = o + tok * 96 + g * 32 + ch * 16;
            #pragma unroll
            for (int nf = 0; nf < 2; nf++) {
                int co = nf * 8 + tig * 2;
                float v0 = acc[nf][hbit * 2], v1 = acc[nf][hbit * 2 + 1];
                *(__nv_bfloat162*)(orow + co) = __floats2bfloat162_rn(v0, v1);
                int bkt = ((ch * 2 + nf) >= nf_thresh) ? 1 : 0;
                gnS[bkt] += v0 + v1;
                gnQ[bkt] += v0 * v0 + v1 * v1;
            }
        }
    }

    redg[0][tid] = gnS[0]; redg[1][tid] = gnQ[0];
    redg[2][tid] = gnS[1]; redg[3][tid] = gnQ[1];
    __syncthreads();
    for (int off = 128; off; off >>= 1) {
        if (tid < off) {
            #pragma unroll
            for (int j = 0; j < 4; j++) redg[j][tid] += redg[j][tid + off];
        }
        __syncthreads();
    }
    if (tid == 0) {
        part2[bid * 4 + 0] = redg[0][0];
        part2[bid * 4 + 1] = redg[1][0];
        part2[bid * 4 + 2] = redg[2][0];
        part2[bid * 4 + 3] = redg[3][0];
    }
}

// ---------------- GN stats combine (deterministic, from conv partials) ------
__global__ void gncomb_kernel(const float* __restrict__ part2, float* __restrict__ stats) {
    int t = threadIdx.x;
    if (t < 16) {
        int b = t >> 2, gi = t & 3;
        int gA = -1, kA = 0, gB = -1, kB = 0;
        if (gi == 0) { gA = 0; kA = 0; }
        else if (gi == 1) { gA = 0; kA = 1; gB = 1; kB = 0; }
        else if (gi == 2) { gA = 1; kA = 1; gB = 2; kB = 0; }
        else { gA = 2; kA = 1; }
        double s = 0.0, q2 = 0.0;
        for (int tile = 0; tile < 49; tile++) {
            int base = ((b * 49 + tile) * 3 + gA) * 4 + kA * 2;
            s += (double)part2[base]; q2 += (double)part2[base + 1];
        }
        if (gB >= 0) {
            for (int tile = 0; tile < 49; tile++) {
                int base = ((b * 49 + tile) * 3 + gB) * 4 + kB * 2;
                s += (double)part2[base]; q2 += (double)part2[base + 1];
            }
        }
        double N = 24.0 * 50176.0;
        double mu  = s / N;
        double var = q2 / N - mu * mu;
        stats[t * 2]     = (float)mu;
        stats[t * 2 + 1] = (float)(1.0 / sqrt(var + 1e-5));
    }
}

// ---------------- merged weight prep ----------------------------------------
__global__ void prep_kernel(const float* __restrict__ qkv_w, const float* __restrict__ proj_w,
                            const float* __restrict__ convp_w, const float* __restrict__ fc1_w,
                            const float* __restrict__ fc2_w, const float* __restrict__ conv3_w,
                            __nv_bfloat16* wq, __nv_bfloat16* wp, __nv_bfloat16* wc,
                            __nv_bfloat16* w1, __nv_bfloat16* w2, __nv_bfloat16* wc3) {
    int i = blockIdx.x * 256 + threadIdx.x;
    if (i < 27648) { wq[i] = __float2bfloat16(qkv_w[i]); return; }
    i -= 27648;
    if (i < 9216)  { wp[i] = __float2bfloat16(proj_w[i]); return; }
    i -= 9216;
    if (i < 9216)  { wc[i] = __float2bfloat16(convp_w[i]); return; }
    i -= 9216;
    if (i < 36864) { w1[i] = __float2bfloat16(fc1_w[i]); return; }
    i -= 36864;
    if (i < 36864) { w2[i] = __float2bfloat16(fc2_w[i]); return; }
    i -= 36864;
    if (i < 82944) {
        int co = i / 864, r = i % 864;
        int tap = r >> 5, ci = r & 31;
        wc3[i] = __float2bfloat16(conv3_w[co * 864 + ci * 27 + tap]);
    }
}

// ---------------- driver -----------------------------------------------------
extern "C" void kernel_launch(void* const* d_in, const int* in_sizes, int n_in,
                              void* d_out, int out_size) {
    const float* x       = (const float*)d_in[0];
    const float* n1w     = (const float*)d_in[1];
    const float* n1b     = (const float*)d_in[2];
    const float* qkv_w   = (const float*)d_in[3];
    const float* proj_w  = (const float*)d_in[4];
    const float* proj_b  = (const float*)d_in[5];
    const float* conv3_w = (const float*)d_in[6];
    const float* gn_w    = (const float*)d_in[7];
    const float* gn_b    = (const float*)d_in[8];
    const float* convp_w = (const float*)d_in[9];
    const float* n2w     = (const float*)d_in[10];
    const float* n2b     = (const float*)d_in[11];
    const float* fc1_w   = (const float*)d_in[12];
    const float* fc1_b   = (const float*)d_in[13];
    const float* fc2_w   = (const float*)d_in[14];
    const float* fc2_b   = (const float*)d_in[15];
    float* out = (float*)d_out;

    float *p_x1, *p_x2, *p_part2, *p_stats;
    __nv_bfloat16 *p_convb, *p_qkvb, *p_xnb, *p_attb, *p_x1b;
    __nv_bfloat16 *p_wq, *p_wp, *p_wc, *p_w1, *p_w2, *p_wc3;
    cudaGetSymbolAddress((void**)&p_x1,   g_x1);
    cudaGetSymbolAddress((void**)&p_x2,   g_x2);
    cudaGetSymbolAddress((void**)&p_part2,g_part2);
    cudaGetSymbolAddress((void**)&p_stats,g_stats);
    cudaGetSymbolAddress((void**)&p_convb,g_convb);
    cudaGetSymbolAddress((void**)&p_qkvb, g_qkvb);
    cudaGetSymbolAddress((void**)&p_xnb,  g_xnb);
    cudaGetSymbolAddress((void**)&p_attb, g_attb);
    cudaGetSymbolAddress((void**)&p_x1b,  g_x1b);
    cudaGetSymbolAddress((void**)&p_wq,   g_wq);
    cudaGetSymbolAddress((void**)&p_wp,   g_wp);
    cudaGetSymbolAddress((void**)&p_wc,   g_wc);
    cudaGetSymbolAddress((void**)&p_w1,   g_w1);
    cudaGetSymbolAddress((void**)&p_w2,   g_w2);
    cudaGetSymbolAddress((void**)&p_wc3,  g_wc3);

    const int CONV_SMEM = 32 * WP3 * 2 + 3 * 4000 * 2;   // 79808
    const int FC_SMEM   = 26624 + 19968 + 19968 + 26624; // 93184
    cudaFuncSetAttribute(conv3t_kernel, cudaFuncAttributeMaxDynamicSharedMemorySize, CONV_SMEM);
    cudaFuncSetAttribute(fc12_kernel,   cudaFuncAttributeMaxDynamicSharedMemorySize, FC_SMEM);

    // 0) merged weight prep
    prep_kernel<<<(202752 + 255) / 256, 256>>>(qkv_w, proj_w, convp_w, fc1_w, fc2_w, conv3_w,
                                               p_wq, p_wp, p_wc, p_w1, p_w2, p_wc3);
    // 1) qkv = LN1(x) @ qkv_w^T -> bf16
    tgemm<3,4,1><<<1568, 256>>>(x, p_wq, nullptr, nullptr, p_qkvb, nullptr, n1w, n1b);
    // 2) attention (vectorized bf16)
    attn_kernel<<<dim3(2048, 3), 224>>>(p_qkvb, p_attb);
    // 3) x1 = x + attn @ proj_w^T + proj_b
    tgemm<1,3,0><<<1568, 256>>>(p_attb, p_wp, proj_b, x, p_x1, p_x1b, nullptr, nullptr);
    // 4) grouped conv (256 thr, co-split warps, fused GN partials, bf16 out)
    conv3t_kernel<<<588, 256, CONV_SMEM>>>(p_x1b, p_wc3, p_convb, p_part2);
    // 5) GN stats combine (deterministic)
    gncomb_kernel<<<1, 16>>>(p_part2, p_stats);
    // 6) fused: x2 = x1 + relu(GN(conv)) @ convp^T ; xnb = LN2(x2)
    convp_kernel<<<1568, 256>>>(p_convb, p_wc, p_stats, gn_w, gn_b, p_x1, n2w, n2b, p_x2, p_xnb);
    // 7) fused MLP
    fc12_kernel<<<1568, 256, FC_SMEM>>>(p_xnb, p_w1, p_w2, fc1_b, fc2_b, p_x2, out);
}

// round 14
// speedup vs baseline: 1.4828x; 1.0220x over previous
#include <cuda_runtime.h>
#include <cuda_bf16.h>
#include <math.h>
#include <cstdint>

// ---------------- problem constants ----------------
#define NTOK 200704           // 4*16*56*56

// ---------------- scratch (static device globals; allowed) ----------------
__device__ __align__(16) float g_x1  [NTOK*96];
__device__ __align__(16) float g_x2  [NTOK*96];
__device__ __align__(16) float g_part2[588*4];
__device__ __align__(16) float g_stats[16*2];
__device__ __align__(16) __nv_bfloat16 g_convb[NTOK*96];
__device__ __align__(16) __nv_bfloat16 g_qkvb[NTOK*288];
__device__ __align__(16) __nv_bfloat16 g_xnb [NTOK*96];
__device__ __align__(16) __nv_bfloat16 g_attb[NTOK*96];
__device__ __align__(16) __nv_bfloat16 g_x1b [NTOK*96];
__device__ __align__(16) __nv_bfloat16 g_wq  [288*96];
__device__ __align__(16) __nv_bfloat16 g_wp  [96*96];
__device__ __align__(16) __nv_bfloat16 g_wc  [96*96];
__device__ __align__(16) __nv_bfloat16 g_w1  [384*96];
__device__ __align__(16) __nv_bfloat16 g_w2  [96*384];
__device__ __align__(16) __nv_bfloat16 g_wc3 [96*864];

// ---------------- warp-MMA helpers ------------------------------------------
__device__ __forceinline__ uint32_t smem_u32(const void* p) {
    uint32_t a;
    asm("{ .reg .u64 t; cvta.to.shared.u64 t, %1; cvt.u32.u64 %0, t; }" : "=r"(a) : "l"(p));
    return a;
}
__device__ __forceinline__ void ldsm_x4(uint32_t* r, uint32_t addr) {
    asm volatile("ldmatrix.sync.aligned.m8n8.x4.shared.b16 {%0,%1,%2,%3}, [%4];"
        : "=r"(r[0]), "=r"(r[1]), "=r"(r[2]), "=r"(r[3]) : "r"(addr));
}
__device__ __forceinline__ void mma16816(float* d, const uint32_t* a, const uint32_t* b) {
    asm volatile(
        "mma.sync.aligned.m16n8k16.row.col.f32.bf16.bf16.f32 "
        "{%0,%1,%2,%3}, {%4,%5,%6,%7}, {%8,%9}, {%0,%1,%2,%3};"
        : "+f"(d[0]), "+f"(d[1]), "+f"(d[2]), "+f"(d[3])
        : "r"(a[0]), "r"(a[1]), "r"(a[2]), "r"(a[3]), "r"(b[0]), "r"(b[1]));
}
__device__ __forceinline__ float gelu_exact(float v) {
    return 0.5f * v * (1.f + erff(v * 0.70710678118654752f));
}

// ---------------- tensor-core GEMM (K=96), M-tile 128 -----------------------
// PROLOG 0: A bf16 load. PROLOG 1: A fp32 + fused LayerNorm -> bf16.
// EPI: 3 = +bias+resid fp32 AND bf16 copy; 4 = bf16 store.
template<int NCH, int EPI, int PROLOG>
__global__ __launch_bounds__(256)
void tgemm(const void* __restrict__ Ax, const __nv_bfloat16* __restrict__ W,
           const float* __restrict__ bias, const float* __restrict__ resid,
           void* __restrict__ outv, __nv_bfloat16* __restrict__ out2,
           const float* __restrict__ lnw, const float* __restrict__ lnb) {
    constexpr int PITCH = 104;
    constexpr int NOtot = 96 * NCH;
    __shared__ __align__(16) __nv_bfloat16 As[128 * PITCH];
    __shared__ __align__(16) __nv_bfloat16 Bs[96 * PITCH];
    const int tid = threadIdx.x;
    const int wid = tid >> 5, lane = tid & 31;
    const int warpM = wid & 3, warpN = wid >> 2;
    const long row0 = (long)blockIdx.x * 128;

    if (PROLOG == 0) {
        const __nv_bfloat16* A = (const __nv_bfloat16*)Ax;
        #pragma unroll
        for (int it = 0; it < 6; it++) {
            int idx = tid + it * 256;
            int r = idx / 12, k = (idx % 12) * 8;
            uint4 v = *(const uint4*)(A + (row0 + r) * 96 + k);
            *(uint4*)(&As[r * PITCH + k]) = v;
        }
    } else {
        const int r = tid >> 1, half = tid & 1;
        const float* xr = (const float*)Ax + (row0 + r) * 96 + half * 48;
        float vb[48];
        float s = 0.f, q2 = 0.f;
        #pragma unroll
        for (int i = 0; i < 12; i++) {
            float4 f = *(const float4*)(xr + i * 4);
            vb[i*4] = f.x; vb[i*4+1] = f.y; vb[i*4+2] = f.z; vb[i*4+3] = f.w;
            s  += f.x + f.y + f.z + f.w;
            q2 += f.x*f.x + f.y*f.y + f.z*f.z + f.w*f.w;
        }
        s  += __shfl_xor_sync(0xFFFFFFFFu, s, 1);
        q2 += __shfl_xor_sync(0xFFFFFFFFu, q2, 1);
        float mu = s * (1.f / 96.f);
        float var = q2 * (1.f / 96.f) - mu * mu;
        float rs = rsqrtf(var + 1e-5f);
        #pragma unroll
        for (int j = 0; j < 48; j += 2) {
            int c = half * 48 + j;
            float n0 = (vb[j]   - mu) * rs * lnw[c]     + lnb[c];
            float n1 = (vb[j+1] - mu) * rs * lnw[c + 1] + lnb[c + 1];
            *(__nv_bfloat162*)(&As[r * PITCH + c]) = __floats2bfloat162_rn(n0, n1);
        }
    }

    const uint32_t smA = smem_u32(As), smB = smem_u32(Bs);
    const int t8 = lane & 7, tq = lane >> 3;
    const int rowA_base = warpM * 32 + t8 + (tq & 1) * 8;
    const int koffA = (tq >> 1) * 8;
    uint32_t offA[2];
    #pragma unroll
    for (int mf = 0; mf < 2; mf++)
        offA[mf] = smA + (uint32_t)(((rowA_base + mf * 16) * PITCH + koffA) * 2);
    const int rowB_base = warpN * 48 + t8 + (tq >> 1) * 8;
    const int koffB = (tq & 1) * 8;
    uint32_t offB[3];
    #pragma unroll
    for (int np = 0; np < 3; np++)
        offB[np] = smB + (uint32_t)(((rowB_base + np * 16) * PITCH + koffB) * 2);
    const int g = lane >> 2, tig = lane & 3;

    #pragma unroll
    for (int nc = 0; nc < NCH; nc++) {
        const int col0 = nc * 96;
        if (nc) __syncthreads();
        for (int idx = tid; idx < 96 * 12; idx += 256) {
            int n = idx / 12, k = (idx % 12) * 8;
            uint4 v = *(const uint4*)(W + (long)(col0 + n) * 96 + k);
            *(uint4*)(&Bs[n * PITCH + k]) = v;
        }
        __syncthreads();

        float acc[2][6][4];
        #pragma unroll
        for (int i = 0; i < 2; i++)
            #pragma unroll
            for (int j = 0; j < 6; j++)
                #pragma unroll
                for (int q = 0; q < 4; q++) acc[i][j][q] = 0.f;
        #pragma unroll
        for (int ks = 0; ks < 6; ks++) {
            uint32_t af[2][4], bf[3][4];
            ldsm_x4(af[0], offA[0] + ks * 32);
            ldsm_x4(af[1], offA[1] + ks * 32);
            ldsm_x4(bf[0], offB[0] + ks * 32);
            ldsm_x4(bf[1], offB[1] + ks * 32);
            ldsm_x4(bf[2], offB[2] + ks * 32);
            #pragma unroll
            for (int mf = 0; mf < 2; mf++)
                #pragma unroll
                for (int np = 0; np < 3; np++) {
                    mma16816(acc[mf][np * 2 + 0], af[mf], &bf[np][0]);
                    mma16816(acc[mf][np * 2 + 1], af[mf], &bf[np][2]);
                }
        }

        #pragma unroll
        for (int mf = 0; mf < 2; mf++) {
            #pragma unroll
            for (int nf = 0; nf < 6; nf++) {
                int col = col0 + warpN * 48 + nf * 8 + tig * 2;
                #pragma unroll
                for (int h = 0; h < 2; h++) {
                    long row = row0 + warpM * 32 + mf * 16 + g + h * 8;
                    float v0 = acc[mf][nf][h * 2 + 0];
                    float v1 = acc[mf][nf][h * 2 + 1];
                    if (EPI == 3) {
                        if (bias) { v0 += bias[col]; v1 += bias[col + 1]; }
                        const float2 rr = *(const float2*)(resid + row * NOtot + col);
                        v0 += rr.x; v1 += rr.y;
                        *(float2*)((float*)outv + row * NOtot + col) = make_float2(v0, v1);
                        *(__nv_bfloat162*)(out2 + row * NOtot + col) = __floats2bfloat162_rn(v0, v1);
                    } else {
                        *(__nv_bfloat162*)((__nv_bfloat16*)outv + row * NOtot + col) = __floats2bfloat162_rn(v0, v1);
                    }
                }
            }
        }
    }
}

// ---------------- multi-dilate local attention (vectorized bf16) ------------
__global__ void attn_kernel(const __nv_bfloat16* __restrict__ qkv, __nv_bfloat16* __restrict__ outb) {
    __shared__ __align__(16) __nv_bfloat16 ks[98 * 32];
    __shared__ __align__(16) __nv_bfloat16 vs[98 * 32];
    __shared__ int toks[98];
    int win = blockIdx.x;
    int dil = blockIdx.y + 1;
    int choff = blockIdx.y * 32;
    int tid = threadIdx.x;
    if (tid < 98) {
        int b  = win >> 9;
        int dq = (win >> 6) & 7;
        int hq = (win >> 3) & 7;
        int wq = win & 7;
        int wd = tid / 49, rem = tid % 49;
        int wh = rem / 7, ww = rem % 7;
        int d = dq * 2 + wd, h = hq * 7 + wh, w = wq * 7 + ww;
        toks[tid] = ((b * 16 + d) * 56 + h) * 56 + w;
    }
    __syncthreads();
    for (int idx = tid; idx < 98 * 8; idx += 224) {
        int n = idx >> 3, sub = idx & 7;
        int isv = sub >> 2, c8 = (sub & 3) * 8;
        long base = (long)toks[n] * 288 + choff + (isv ? 192 : 96) + c8;
        uint4 v = *(const uint4*)(qkv + base);
        *(uint4*)((isv ? vs : ks) + n * 32 + c8) = v;
    }
    __syncthreads();
    if (tid < 196) {
        int n = tid >> 1, head = tid & 1;
        long qbase = (long)toks[n] * 288 + choff + head * 16;
        float q[16];
        {
            uint4 qa = *(const uint4*)(qkv + qbase);
            uint4 qb = *(const uint4*)(qkv + qbase + 8);
            const __nv_bfloat162* qp = (const __nv_bfloat162*)&qa;
            #pragma unroll
            for (int i = 0; i < 4; i++) {
                float2 f = __bfloat1622float2(qp[i]);
                q[i * 2] = f.x; q[i * 2 + 1] = f.y;
            }
            qp = (const __nv_bfloat162*)&qb;
            #pragma unroll
            for (int i = 0; i < 4; i++) {
                float2 f = __bfloat1622float2(qp[i]);
                q[8 + i * 2] = f.x; q[8 + i * 2 + 1] = f.y;
            }
        }
        float lr[3]; int mm[3];
        #pragma unroll
        for (int j = 0; j < 3; j++) {
            int m = n + (j - 1) * dil;
            mm[j] = m;
            float s = 0.f;
            if (m >= 0 && m < 98) {
                const __nv_bfloat162* kr = (const __nv_bfloat162*)&ks[m * 32 + head * 16];
                #pragma unroll
                for (int c = 0; c < 8; c++) {
                    float2 f = __bfloat1622float2(kr[c]);
                    s += q[c * 2] * f.x + q[c * 2 + 1] * f.y;
                }
            }
            lr[j] = s * 0.25f;
        }
        float mx = fmaxf(0.f, fmaxf(lr[0], fmaxf(lr[1], lr[2])));
        float e[3];
        e[0] = expf(lr[0] - mx); e[1] = expf(lr[1] - mx); e[2] = expf(lr[2] - mx);
        float denom = 6.f * expf(-mx) + e[0] + e[1] + e[2];
        float o[16];
        #pragma unroll
        for (int c = 0; c < 16; c++) o[c] = 0.f;
        #pragma unroll
        for (int j = 0; j < 3; j++) {
            int m = mm[j];
            if (m >= 0 && m < 98) {
                float a = e[j] / denom;
                const __nv_bfloat162* vr = (const __nv_bfloat162*)&vs[m * 32 + head * 16];
                #pragma unroll
                for (int c = 0; c < 8; c++) {
                    float2 f = __bfloat1622float2(vr[c]);
                    o[c * 2]     += a * f.x;
                    o[c * 2 + 1] += a * f.y;
                }
            }
        }
        long obase = (long)toks[n] * 96 + choff + head * 16;
        #pragma unroll
        for (int c = 0; c < 8; c++)
            *(__nv_bfloat162*)(outb + obase + c * 2) = __floats2bfloat162_rn(o[c * 2], o[c * 2 + 1]);
    }
}

// ---------------- fused 1x1-conv GEMM: GN+ReLU prologue, LN2 epilogue -------
__global__ __launch_bounds__(256)
void convp_kernel(const __nv_bfloat16* __restrict__ convb, const __nv_bfloat16* __restrict__ W,
                  const float* __restrict__ stats, const float* __restrict__ gnw,
                  const float* __restrict__ gnb, const float* __restrict__ x1,
                  const float* __restrict__ n2w, const float* __restrict__ n2b,
                  float* __restrict__ x2, __nv_bfloat16* __restrict__ xnb) {
    constexpr int PITCH = 104;
    __shared__ __align__(16) __nv_bfloat16 As[128 * PITCH];
    __shared__ __align__(16) __nv_bfloat16 Bs[96 * PITCH];
    __shared__ float redS[128][2], redQ[128][2];
    const int tid = threadIdx.x;
    const int wid = tid >> 5, lane = tid & 31;
    const int warpM = wid & 3, warpN = wid >> 2;
    const long row0 = (long)blockIdx.x * 128;

    const int bidx = (int)(row0 / 50176) * 4;
    for (int idx = tid; idx < 128 * 12; idx += 256) {
        int r = idx / 12, k8 = (idx % 12) * 8;
        uint4 cv = *(const uint4*)(convb + (row0 + r) * 96 + k8);
        const __nv_bfloat16* cp = (const __nv_bfloat16*)&cv;
        int gi = bidx + k8 / 24;
        float mu = stats[gi * 2], rs = stats[gi * 2 + 1];
        #pragma unroll
        for (int j = 0; j < 8; j += 2) {
            int c = k8 + j;
            float f0 = fmaxf((__bfloat162float(cp[j])     - mu) * rs * gnw[c]     + gnb[c],     0.f);
            float f1 = fmaxf((__bfloat162float(cp[j + 1]) - mu) * rs * gnw[c + 1] + gnb[c + 1], 0.f);
            *(__nv_bfloat162*)(&As[r * PITCH + c]) = __floats2bfloat162_rn(f0, f1);
        }
    }
    for (int idx = tid; idx < 96 * 12; idx += 256) {
        int n = idx / 12, k = (idx % 12) * 8;
        uint4 v = *(const uint4*)(W + n * 96 + k);
        *(uint4*)(&Bs[n * PITCH + k]) = v;
    }
    __syncthreads();

    float acc[2][6][4];
    #pragma unroll
    for (int i = 0; i < 2; i++)
        #pragma unroll
        for (int j = 0; j < 6; j++)
            #pragma unroll
            for (int q = 0; q < 4; q++) acc[i][j][q] = 0.f;

    const uint32_t smA = smem_u32(As), smB = smem_u32(Bs);
    const int t8 = lane & 7, tq = lane >> 3;
    const int rowA_base = warpM * 32 + t8 + (tq & 1) * 8;
    const int koffA = (tq >> 1) * 8;
    uint32_t offA[2];
    #pragma unroll
    for (int mf = 0; mf < 2; mf++)
        offA[mf] = smA + (uint32_t)(((rowA_base + mf * 16) * PITCH + koffA) * 2);
    const int rowB_base = warpN * 48 + t8 + (tq >> 1) * 8;
    const int koffB = (tq & 1) * 8;
    uint32_t offB[3];
    #pragma unroll
    for (int np = 0; np < 3; np++)
        offB[np] = smB + (uint32_t)(((rowB_base + np * 16) * PITCH + koffB) * 2);

    #pragma unroll
    for (int ks = 0; ks < 6; ks++) {
        uint32_t af[2][4], bf[3][4];
        ldsm_x4(af[0], offA[0] + ks * 32);
        ldsm_x4(af[1], offA[1] + ks * 32);
        ldsm_x4(bf[0], offB[0] + ks * 32);
        ldsm_x4(bf[1], offB[1] + ks * 32);
        ldsm_x4(bf[2], offB[2] + ks * 32);
        #pragma unroll
        for (int mf = 0; mf < 2; mf++)
            #pragma unroll
            for (int np = 0; np < 3; np++) {
                mma16816(acc[mf][np * 2 + 0], af[mf], &bf[np][0]);
                mma16816(acc[mf][np * 2 + 1], af[mf], &bf[np][2]);
            }
    }

    const int g = lane >> 2, tig = lane & 3;
    #pragma unroll
    for (int mf = 0; mf < 2; mf++)
        #pragma unroll
        for (int h = 0; h < 2; h++) {
            int rl = warpM * 32 + mf * 16 + g + h * 8;
            long row = row0 + rl;
            float s = 0.f, q2 = 0.f;
            #pragma unroll
            for (int nf = 0; nf < 6; nf++) {
                int col = warpN * 48 + nf * 8 + tig * 2;
                const float2 rr = *(const float2*)(x1 + row * 96 + col);
                float v0 = acc[mf][nf][h * 2 + 0] + rr.x;
                float v1 = acc[mf][nf][h * 2 + 1] + rr.y;
                acc[mf][nf][h * 2 + 0] = v0;
                acc[mf][nf][h * 2 + 1] = v1;
                s += v0 + v1; q2 += v0 * v0 + v1 * v1;
            }
            s  += __shfl_xor_sync(0xFFFFFFFFu, s, 1);
            q2 += __shfl_xor_sync(0xFFFFFFFFu, q2, 1);
            s  += __shfl_xor_sync(0xFFFFFFFFu, s, 2);
            q2 += __shfl_xor_sync(0xFFFFFFFFu, q2, 2);
            if (tig == 0) { redS[rl][warpN] = s; redQ[rl][warpN] = q2; }
        }
    __syncthreads();

    #pragma unroll
    for (int mf = 0; mf < 2; mf++)
        #pragma unroll
        for (int h = 0; h < 2; h++) {
            int rl = warpM * 32 + mf * 16 + g + h * 8;
            long row = row0 + rl;
            float tot = redS[rl][0] + redS[rl][1];
            float tq2 = redQ[rl][0] + redQ[rl][1];
            float mu = tot * (1.f / 96.f);
            float var = tq2 * (1.f / 96.f) - mu * mu;
            float rs = rsqrtf(var + 1e-5f);
            #pragma unroll
            for (int nf = 0; nf < 6; nf++) {
                int col = warpN * 48 + nf * 8 + tig * 2;
                float v0 = acc[mf][nf][h * 2 + 0];
                float v1 = acc[mf][nf][h * 2 + 1];
                *(float2*)(x2 + row * 96 + col) = make_float2(v0, v1);
                float n0 = (v0 - mu) * rs * n2w[col]     + n2b[col];
                float n1 = (v1 - mu) * rs * n2w[col + 1] + n2b[col + 1];
                *(__nv_bfloat162*)(xnb + row * 96 + col) = __floats2bfloat162_rn(n0, n1);
            }
        }
}

// ---------------- fused MLP: out = x2 + gelu(xn@W1^T+b1) @ W2^T + b2 --------
__global__ __launch_bounds__(256, 2)
void fc12_kernel(const __nv_bfloat16* __restrict__ xnb, const __nv_bfloat16* __restrict__ w1,
                 const __nv_bfloat16* __restrict__ w2, const float* __restrict__ b1,
                 const float* __restrict__ b2, const float* __restrict__ x2,
                 float* __restrict__ out) {
    constexpr int PITCH = 104;
    extern __shared__ __align__(16) char sm[];
    __nv_bfloat16* As  = (__nv_bfloat16*)sm;
    __nv_bfloat16* Bs1 = (__nv_bfloat16*)(sm + 26624);
    __nv_bfloat16* Bs2 = (__nv_bfloat16*)(sm + 46592);
    __nv_bfloat16* Hs  = (__nv_bfloat16*)(sm + 66560);
    const int tid = threadIdx.x;
    const int wid = tid >> 5, lane = tid & 31;
    const int warpM = wid & 3, warpN = wid >> 2;
    const long row0 = (long)blockIdx.x * 128;

    #pragma unroll
    for (int it = 0; it < 6; it++) {
        int idx = tid + it * 256;
        int r = idx / 12, k = (idx % 12) * 8;
        uint4 v = *(const uint4*)(xnb + (row0 + r) * 96 + k);
        *(uint4*)(&As[r * PITCH + k]) = v;
    }

    const uint32_t smA = smem_u32(As), smB1 = smem_u32(Bs1), smB2 = smem_u32(Bs2), smH = smem_u32(Hs);
    const int t8 = lane & 7, tq = lane >> 3;
    const int rowA_base = warpM * 32 + t8 + (tq & 1) * 8;
    const int koffA = (tq >> 1) * 8;
    uint32_t offA[2], offH[2];
    #pragma unroll
    for (int mf = 0; mf < 2; mf++) {
        offA[mf] = smA + (uint32_t)(((rowA_base + mf * 16) * PITCH + koffA) * 2);
        offH[mf] = smH + (uint32_t)(((rowA_base + mf * 16) * PITCH + koffA) * 2);
    }
    const int rowB_base = warpN * 48 + t8 + (tq >> 1) * 8;
    const int koffB = (tq & 1) * 8;
    uint32_t offB1[3], offB2[3];
    #pragma unroll
    for (int np = 0; np < 3; np++) {
        offB1[np] = smB1 + (uint32_t)(((rowB_base + np * 16) * PITCH + koffB) * 2);
        offB2[np] = smB2 + (uint32_t)(((rowB_base + np * 16) * PITCH + koffB) * 2);
    }
    const int g = lane >> 2, tig = lane & 3;

    float acc2[2][6][4];
    #pragma unroll
    for (int i = 0; i < 2; i++)
        #pragma unroll
        for (int j = 0; j < 6; j++)
            #pragma unroll
            for (int q = 0; q < 4; q++) acc2[i][j][q] = 0.f;

    for (int nc = 0; nc < 4; nc++) {
        __syncthreads();
        for (int idx = tid; idx < 96 * 12; idx += 256) {
            int n = idx / 12, k = (idx % 12) * 8;
            uint4 v1 = *(const uint4*)(w1 + (long)(nc * 96 + n) * 96 + k);
            *(uint4*)(&Bs1[n * PITCH + k]) = v1;
            uint4 v2 = *(const uint4*)(w2 + (long)n * 384 + nc * 96 + k);
            *(uint4*)(&Bs2[n * PITCH + k]) = v2;
        }
        __syncthreads();

        float acc1[2][6][4];
        #pragma unroll
        for (int i = 0; i < 2; i++)
            #pragma unroll
            for (int j = 0; j < 6; j++)
                #pragma unroll
                for (int q = 0; q < 4; q++) acc1[i][j][q] = 0.f;
        #pragma unroll
        for (int ks = 0; ks < 6; ks++) {
            uint32_t af[2][4], bf[3][4];
            ldsm_x4(af[0], offA[0] + ks * 32);
            ldsm_x4(af[1], offA[1] + ks * 32);
            ldsm_x4(bf[0], offB1[0] + ks * 32);
            ldsm_x4(bf[1], offB1[1] + ks * 32);
            ldsm_x4(bf[2], offB1[2] + ks * 32);
            #pragma unroll
            for (int mf = 0; mf < 2; mf++)
                #pragma unroll
                for (int np = 0; np < 3; np++) {
                    mma16816(acc1[mf][np * 2 + 0], af[mf], &bf[np][0]);
                    mma16816(acc1[mf][np * 2 + 1], af[mf], &bf[np][2]);
                }
        }
        #pragma unroll
        for (int mf = 0; mf < 2; mf++)
            #pragma unroll
            for (int nf = 0; nf < 6; nf++) {
                int hcol = warpN * 48 + nf * 8 + tig * 2;
                float bb0 = b1[nc * 96 + hcol], bb1 = b1[nc * 96 + hcol + 1];
                #pragma unroll
                for (int h = 0; h < 2; h++) {
                    int rl = warpM * 32 + mf * 16 + g + h * 8;
                    float v0 = gelu_exact(acc1[mf][nf][h * 2 + 0] + bb0);
                    float v1 = gelu_exact(acc1[mf][nf][h * 2 + 1] + bb1);
                    *(__nv_bfloat162*)(&Hs[rl * PITCH + hcol]) = __floats2bfloat162_rn(v0, v1);
                }
            }
        __syncthreads();

        #pragma unroll
        for (int ks = 0; ks < 6; ks++) {
            uint32_t af[2][4], bf[3][4];
            ldsm_x4(af[0], offH[0] + ks * 32);
            ldsm_x4(af[1], offH[1] + ks * 32);
            ldsm_x4(bf[0], offB2[0] + ks * 32);
            ldsm_x4(bf[1], offB2[1] + ks * 32);
            ldsm_x4(bf[2], offB2[2] + ks * 32);
            #pragma unroll
            for (int mf = 0; mf < 2; mf++)
                #pragma unroll
                for (int np = 0; np < 3; np++) {
                    mma16816(acc2[mf][np * 2 + 0], af[mf], &bf[np][0]);
                    mma16816(acc2[mf][np * 2 + 1], af[mf], &bf[np][2]);
                }
        }
    }

    #pragma unroll
    for (int mf = 0; mf < 2; mf++)
        #pragma unroll
        for (int nf = 0; nf < 6; nf++) {
            int col = warpN * 48 + nf * 8 + tig * 2;
            #pragma unroll
            for (int h = 0; h < 2; h++) {
                long row = row0 + warpM * 32 + mf * 16 + g + h * 8;
                const float2 rr = *(const float2*)(x2 + row * 96 + col);
                float v0 = acc2[mf][nf][h * 2 + 0] + b2[col]     + rr.x;
                float v1 = acc2[mf][nf][h * 2 + 1] + b2[col + 1] + rr.y;
                *(float2*)(out + row * 96 + col) = make_float2(v0, v1);
            }
        }
}

// ---------------- tensor-core grouped 3x3x3 conv (256 thr, pipelined) -------
#define CVP 40
#define WP3 872
__global__ __launch_bounds__(256)
void conv3t_kernel(const __nv_bfloat16* __restrict__ x, const __nv_bfloat16* __restrict__ wc3,
                   __nv_bfloat16* __restrict__ o, float* __restrict__ part2) {
    extern __shared__ __align__(16) char smc[];
    __nv_bfloat16* ws   = (__nv_bfloat16*)smc;
    __nv_bfloat16* in_s = (__nv_bfloat16*)(smc + 32 * WP3 * 2);
    __shared__ float redg[4][256];
    int bid = blockIdx.x;
    int g = bid % 3; int t = bid / 3;
    int tw = t % 7, th = (t / 7) % 7, b = t / 49;
    int h0 = th * 8, w0 = tw * 8;
    int tid = threadIdx.x, wid = tid >> 5, lane = tid & 31;
    const int wrp2 = wid & 3;          // position group (rows 2*wrp2, 2*wrp2+1)
    const int ch   = wid >> 2;         // co half: 0 -> co 0..15, 1 -> co 16..31

    for (int idx = tid; idx < 32 * 108; idx += 256) {
        int row = idx / 108, kc = (idx % 108) * 8;
        uint4 v = *(const uint4*)(wc3 + (g * 32 + row) * 864 + kc);
        *(uint4*)(ws + row * WP3 + kc) = v;
    }

    // this thread's (up to 2) plane-load positions
    const int pos0 = tid >> 2,          c80 = (tid & 3) * 8;
    const int hh0 = pos0 / 10,          ww0s = pos0 % 10;
    const int ih0 = h0 - 1 + hh0,       iw0 = w0 - 1 + ww0s;
    const bool ok0xy = (ih0 >= 0 && ih0 < 56 && iw0 >= 0 && iw0 < 56);
    const int tid2 = tid + 256;                       // 400 items, 256 threads
    const int pos1 = tid2 >> 2,         c81 = (tid2 & 3) * 8;
    const int hh1 = pos1 / 10,          ww1s = pos1 % 10;
    const int ih1 = h0 - 1 + hh1,       iw1 = w0 - 1 + ww1s;
    const bool have1 = (tid2 < 400);
    const bool ok1xy = have1 && (ih1 >= 0 && ih1 < 56 && iw1 >= 0 && iw1 < 56);

    auto load_plane = [&](int dde, int slot) {      // prologue (synchronous)
        uint4 v = make_uint4(0, 0, 0, 0);
        if (dde >= 0 && dde < 16 && ok0xy)
            v = *(const uint4*)(x + ((long)((b * 16 + dde) * 56 + ih0) * 56 + iw0) * 96 + g * 32 + c80);
        *(uint4*)(in_s + slot * 4000 + (hh0 * 10 + ww0s) * CVP + c80) = v;
        if (have1) {
            uint4 v2 = make_uint4(0, 0, 0, 0);
            if (dde >= 0 && dde < 16 && ok1xy)
                v2 = *(const uint4*)(x + ((long)((b * 16 + dde) * 56 + ih1) * 56 + iw1) * 96 + g * 32 + c81);
            *(uint4*)(in_s + slot * 4000 + (hh1 * 10 + ww1s) * CVP + c81) = v2;
        }
    };
    load_plane(-1, 2);
    load_plane(0,  0);
    load_plane(1,  1);

    const int t8 = lane & 7, tq = lane >> 3;
    const int mrow = t8 + (tq & 1) * 8;
    const int p = wrp2 * 16 + mrow;
    const int hr = p >> 3, wc = p & 7;
    const int koffA = (tq >> 1) * 8;
    const uint32_t inb = smem_u32(in_s);
    const uint32_t aoff = inb + (uint32_t)(((hr * 10 + wc) * CVP + koffA) * 2);
    const int nr = ch * 16 + t8 + (tq >> 1) * 8;
    const int koffB = (tq & 1) * 8;
    const uint32_t wsb = smem_u32(ws);
    const uint32_t boff = wsb + (uint32_t)((nr * WP3 + koffB) * 2);
    const int g2 = lane >> 2, tig = lane & 3;
    const int nf_thresh = 3 - g;        // GN split over global nf (0..3)

    float gnS[2] = {0.f, 0.f}, gnQ[2] = {0.f, 0.f};
    __syncthreads();

    for (int dcur = 0; dcur < 16; dcur++) {
        // prefetch plane dcur+2 into registers (latency hidden by compute)
        uint4 pre0 = make_uint4(0, 0, 0, 0), pre1 = make_uint4(0, 0, 0, 0);
        {
            int dde = dcur + 2;
            if (dde < 16 && ok0xy)
                pre0 = *(const uint4*)(x + ((long)((b * 16 + dde) * 56 + ih0) * 56 + iw0) * 96 + g * 32 + c80);
            if (dde < 16 && ok1xy)
                pre1 = *(const uint4*)(x + ((long)((b * 16 + dde) * 56 + ih1) * 56 + iw1) * 96 + g * 32 + c81);
        }

        int slots[3] = { (dcur + 2) % 3, dcur % 3, (dcur + 1) % 3 };

        float acc[2][2][4];   // [nf][s-half][frag]
        #pragma unroll
        for (int i = 0; i < 2; i++)
            #pragma unroll
            for (int s2 = 0; s2 < 2; s2++)
                #pragma unroll
                for (int q = 0; q < 4; q++) acc[i][s2][q] = 0.f;

        #pragma unroll
        for (int kd = 0; kd < 3; kd++)
            #pragma unroll
            for (int kh = 0; kh < 3; kh++)
                #pragma unroll
                for (int kw = 0; kw < 3; kw++) {
                    uint32_t abase = aoff + (uint32_t)((slots[kd] * 4000 + (kh * 10 + kw) * CVP) * 2);
                    int tap = kd * 9 + kh * 3 + kw;
                    #pragma unroll
                    for (int s = 0; s < 2; s++) {
                        uint32_t af[4], bfr[4];
                        ldsm_x4(af, abase + s * 32);
                        ldsm_x4(bfr, boff + (uint32_t)((tap * 32 + s * 16) * 2));
                        mma16816(acc[0][s], af, &bfr[0]);
                        mma16816(acc[1][s], af, &bfr[2]);
                    }
                }

        #pragma unroll
        for (int hbit = 0; hbit < 2; hbit++) {
            long tok = ((long)(b * 16 + dcur) * 56 + (h0 + 2 * wrp2 + hbit)) * 56 + (w0 + g2);
            __nv_bfloat16* orow = o + tok * 96 + g * 32 + ch * 16;
            #pragma unroll
            for (int nf = 0; nf < 2; nf++) {
                int co = nf * 8 + tig * 2;
                float v0 = acc[nf][0][hbit * 2]     + acc[nf][1][hbit * 2];
                float v1 = acc[nf][0][hbit * 2 + 1] + acc[nf][1][hbit * 2 + 1];
                *(__nv_bfloat162*)(orow + co) = __floats2bfloat162_rn(v0, v1);
                int bkt = ((ch * 2 + nf) >= nf_thresh) ? 1 : 0;
                gnS[bkt] += v0 + v1;
                gnQ[bkt] += v0 * v0 + v1 * v1;
            }
        }

        __syncthreads();   // all reads of slot (dcur+2)%3 done
        {
            int slot = (dcur + 2) % 3;
            *(uint4*)(in_s + slot * 4000 + (hh0 * 10 + ww0s) * CVP + c80) = pre0;
            if (have1)
                *(uint4*)(in_s + slot * 4000 + (hh1 * 10 + ww1s) * CVP + c81) = pre1;
        }
        __syncthreads();   // plane dcur+2 visible
    }

    redg[0][tid] = gnS[0]; redg[1][tid] = gnQ[0];
    redg[2][tid] = gnS[1]; redg[3][tid] = gnQ[1];
    __syncthreads();
    for (int off = 128; off; off >>= 1) {
        if (tid < off) {
            #pragma unroll
            for (int j = 0; j < 4; j++) redg[j][tid] += redg[j][tid + off];
        }
        __syncthreads();
    }
    if (tid == 0) {
        part2[bid * 4 + 0] = redg[0][0];
        part2[bid * 4 + 1] = redg[1][0];
        part2[bid * 4 + 2] = redg[2][0];
        part2[bid * 4 + 3] = redg[3][0];
    }
}

// ---------------- GN stats combine (deterministic, from conv partials) ------
__global__ void gncomb_kernel(const float* __restrict__ part2, float* __restrict__ stats) {
    int t = threadIdx.x;
    if (t < 16) {
        int b = t >> 2, gi = t & 3;
        int gA = -1, kA = 0, gB = -1, kB = 0;
        if (gi == 0) { gA = 0; kA = 0; }
        else if (gi == 1) { gA = 0; kA = 1; gB = 1; kB = 0; }
        else if (gi == 2) { gA = 1; kA = 1; gB = 2; kB = 0; }
        else { gA = 2; kA = 1; }
        double s = 0.0, q2 = 0.0;
        for (int tile = 0; tile < 49; tile++) {
            int base = ((b * 49 + tile) * 3 + gA) * 4 + kA * 2;
            s += (double)part2[base]; q2 += (double)part2[base + 1];
        }
        if (gB >= 0) {
            for (int tile = 0; tile < 49; tile++) {
                int base = ((b * 49 + tile) * 3 + gB) * 4 + kB * 2;
                s += (double)part2[base]; q2 += (double)part2[base + 1];
            }
        }
        double N = 24.0 * 50176.0;
        double mu  = s / N;
        double var = q2 / N - mu * mu;
        stats[t * 2]     = (float)mu;
        stats[t * 2 + 1] = (float)(1.0 / sqrt(var + 1e-5));
    }
}

// ---------------- merged weight prep ----------------------------------------
__global__ void prep_kernel(const float* __restrict__ qkv_w, const float* __restrict__ proj_w,
                            const float* __restrict__ convp_w, const float* __restrict__ fc1_w,
                            const float* __restrict__ fc2_w, const float* __restrict__ conv3_w,
                            __nv_bfloat16* wq, __nv_bfloat16* wp, __nv_bfloat16* wc,
                            __nv_bfloat16* w1, __nv_bfloat16* w2, __nv_bfloat16* wc3) {
    int i = blockIdx.x * 256 + threadIdx.x;
    if (i < 27648) { wq[i] = __float2bfloat16(qkv_w[i]); return; }
    i -= 27648;
    if (i < 9216)  { wp[i] = __float2bfloat16(proj_w[i]); return; }
    i -= 9216;
    if (i < 9216)  { wc[i] = __float2bfloat16(convp_w[i]); return; }
    i -= 9216;
    if (i < 36864) { w1[i] = __float2bfloat16(fc1_w[i]); return; }
    i -= 36864;
    if (i < 36864) { w2[i] = __float2bfloat16(fc2_w[i]); return; }
    i -= 36864;
    if (i < 82944) {
        int co = i / 864, r = i % 864;
        int tap = r >> 5, ci = r & 31;
        wc3[i] = __float2bfloat16(conv3_w[co * 864 + ci * 27 + tap]);
    }
}

// ---------------- driver -----------------------------------------------------
extern "C" void kernel_launch(void* const* d_in, const int* in_sizes, int n_in,
                              void* d_out, int out_size) {
    const float* x       = (const float*)d_in[0];
    const float* n1w     = (const float*)d_in[1];
    const float* n1b     = (const float*)d_in[2];
    const float* qkv_w   = (const float*)d_in[3];
    const float* proj_w  = (const float*)d_in[4];
    const float* proj_b  = (const float*)d_in[5];
    const float* conv3_w = (const float*)d_in[6];
    const float* gn_w    = (const float*)d_in[7];
    const float* gn_b    = (const float*)d_in[8];
    const float* convp_w = (const float*)d_in[9];
    const float* n2w     = (const float*)d_in[10];
    const float* n2b     = (const float*)d_in[11];
    const float* fc1_w   = (const float*)d_in[12];
    const float* fc1_b   = (const float*)d_in[13];
    const float* fc2_w   = (const float*)d_in[14];
    const float* fc2_b   = (const float*)d_in[15];
    float* out = (float*)d_out;

    float *p_x1, *p_x2, *p_part2, *p_stats;
    __nv_bfloat16 *p_convb, *p_qkvb, *p_xnb, *p_attb, *p_x1b;
    __nv_bfloat16 *p_wq, *p_wp, *p_wc, *p_w1, *p_w2, *p_wc3;
    cudaGetSymbolAddress((void**)&p_x1,   g_x1);
    cudaGetSymbolAddress((void**)&p_x2,   g_x2);
    cudaGetSymbolAddress((void**)&p_part2,g_part2);
    cudaGetSymbolAddress((void**)&p_stats,g_stats);
    cudaGetSymbolAddress((void**)&p_convb,g_convb);
    cudaGetSymbolAddress((void**)&p_qkvb, g_qkvb);
    cudaGetSymbolAddress((void**)&p_xnb,  g_xnb);
    cudaGetSymbolAddress((void**)&p_attb, g_attb);
    cudaGetSymbolAddress((void**)&p_x1b,  g_x1b);
    cudaGetSymbolAddress((void**)&p_wq,   g_wq);
    cudaGetSymbolAddress((void**)&p_wp,   g_wp);
    cudaGetSymbolAddress((void**)&p_wc,   g_wc);
    cudaGetSymbolAddress((void**)&p_w1,   g_w1);
    cudaGetSymbolAddress((void**)&p_w2,   g_w2);
    cudaGetSymbolAddress((void**)&p_wc3,  g_wc3);

    const int CONV_SMEM = 32 * WP3 * 2 + 3 * 4000 * 2;   // 79808
    const int FC_SMEM   = 26624 + 19968 + 19968 + 26624; // 93184
    cudaFuncSetAttribute(conv3t_kernel, cudaFuncAttributeMaxDynamicSharedMemorySize, CONV_SMEM);
    cudaFuncSetAttribute(fc12_kernel,   cudaFuncAttributeMaxDynamicSharedMemorySize, FC_SMEM);

    // 0) merged weight prep
    prep_kernel<<<(202752 + 255) / 256, 256>>>(qkv_w, proj_w, convp_w, fc1_w, fc2_w, conv3_w,
                                               p_wq, p_wp, p_wc, p_w1, p_w2, p_wc3);
    // 1) qkv = LN1(x) @ qkv_w^T -> bf16
    tgemm<3,4,1><<<1568, 256>>>(x, p_wq, nullptr, nullptr, p_qkvb, nullptr, n1w, n1b);
    // 2) attention (vectorized bf16)
    attn_kernel<<<dim3(2048, 3), 224>>>(p_qkvb, p_attb);
    // 3) x1 = x + attn @ proj_w^T + proj_b
    tgemm<1,3,0><<<1568, 256>>>(p_attb, p_wp, proj_b, x, p_x1, p_x1b, nullptr, nullptr);
    // 4) grouped conv (pipelined prefetch, s-split accumulators, bf16 out)
    conv3t_kernel<<<588, 256, CONV_SMEM>>>(p_x1b, p_wc3, p_convb, p_part2);
    // 5) GN stats combine (deterministic)
    gncomb_kernel<<<1, 16>>>(p_part2, p_stats);
    // 6) fused: x2 = x1 + relu(GN(conv)) @ convp^T ; xnb = LN2(x2)
    convp_kernel<<<1568, 256>>>(p_convb, p_wc, p_stats, gn_w, gn_b, p_x1, n2w, n2b, p_x2, p_xnb);
    // 7) fused MLP
    fc12_kernel<<<1568, 256, FC_SMEM>>>(p_xnb, p_w1, p_w2, fc1_b, fc2_b, p_x2, out);
}

// round 15
// speedup vs baseline: 1.5084x; 1.0172x over previous
#include <cuda_runtime.h>
#include <cuda_bf16.h>
#include <math.h>
#include <cstdint>

// ---------------- problem constants ----------------
#define NTOK 200704           // 4*16*56*56

// ---------------- scratch (static device globals; allowed) ----------------
__device__ __align__(16) float g_x1  [NTOK*96];
__device__ __align__(16) float g_x2  [NTOK*96];
__device__ __align__(16) float g_part2[588*4];
__device__ __align__(16) float g_stats[16*2];
__device__ __align__(16) __nv_bfloat16 g_convb[NTOK*96];
__device__ __align__(16) __nv_bfloat16 g_qkvb[NTOK*288];
__device__ __align__(16) __nv_bfloat16 g_attb[NTOK*96];
__device__ __align__(16) __nv_bfloat16 g_x1b [NTOK*96];
__device__ __align__(16) __nv_bfloat16 g_wq  [288*96];
__device__ __align__(16) __nv_bfloat16 g_wp  [96*96];
__device__ __align__(16) __nv_bfloat16 g_wc  [96*96];
__device__ __align__(16) __nv_bfloat16 g_w1  [384*96];
__device__ __align__(16) __nv_bfloat16 g_w2  [96*384];
__device__ __align__(16) __nv_bfloat16 g_wc3 [96*864];

// ---------------- warp-MMA helpers ------------------------------------------
__device__ __forceinline__ uint32_t smem_u32(const void* p) {
    uint32_t a;
    asm("{ .reg .u64 t; cvta.to.shared.u64 t, %1; cvt.u32.u64 %0, t; }" : "=r"(a) : "l"(p));
    return a;
}
__device__ __forceinline__ void ldsm_x4(uint32_t* r, uint32_t addr) {
    asm volatile("ldmatrix.sync.aligned.m8n8.x4.shared.b16 {%0,%1,%2,%3}, [%4];"
        : "=r"(r[0]), "=r"(r[1]), "=r"(r[2]), "=r"(r[3]) : "r"(addr));
}
__device__ __forceinline__ void mma16816(float* d, const uint32_t* a, const uint32_t* b) {
    asm volatile(
        "mma.sync.aligned.m16n8k16.row.col.f32.bf16.bf16.f32 "
        "{%0,%1,%2,%3}, {%4,%5,%6,%7}, {%8,%9}, {%0,%1,%2,%3};"
        : "+f"(d[0]), "+f"(d[1]), "+f"(d[2]), "+f"(d[3])
        : "r"(a[0]), "r"(a[1]), "r"(a[2]), "r"(a[3]), "r"(b[0]), "r"(b[1]));
}
__device__ __forceinline__ float gelu_exact(float v) {
    return 0.5f * v * (1.f + erff(v * 0.70710678118654752f));
}

// ---------------- tensor-core GEMM (K=96), M-tile 128 -----------------------
// PROLOG 0: A bf16 load. PROLOG 1: A fp32 + fused LayerNorm -> bf16.
// EPI: 3 = +bias+resid fp32 AND bf16 copy; 4 = bf16 store.
template<int NCH, int EPI, int PROLOG>
__global__ __launch_bounds__(256)
void tgemm(const void* __restrict__ Ax, const __nv_bfloat16* __restrict__ W,
           const float* __restrict__ bias, const float* __restrict__ resid,
           void* __restrict__ outv, __nv_bfloat16* __restrict__ out2,
           const float* __restrict__ lnw, const float* __restrict__ lnb) {
    constexpr int PITCH = 104;
    constexpr int NOtot = 96 * NCH;
    __shared__ __align__(16) __nv_bfloat16 As[128 * PITCH];
    __shared__ __align__(16) __nv_bfloat16 Bs[96 * PITCH];
    const int tid = threadIdx.x;
    const int wid = tid >> 5, lane = tid & 31;
    const int warpM = wid & 3, warpN = wid >> 2;
    const long row0 = (long)blockIdx.x * 128;

    if (PROLOG == 0) {
        const __nv_bfloat16* A = (const __nv_bfloat16*)Ax;
        #pragma unroll
        for (int it = 0; it < 6; it++) {
            int idx = tid + it * 256;
            int r = idx / 12, k = (idx % 12) * 8;
            uint4 v = *(const uint4*)(A + (row0 + r) * 96 + k);
            *(uint4*)(&As[r * PITCH + k]) = v;
        }
    } else {
        const int r = tid >> 1, half = tid & 1;
        const float* xr = (const float*)Ax + (row0 + r) * 96 + half * 48;
        float vb[48];
        float s = 0.f, q2 = 0.f;
        #pragma unroll
        for (int i = 0; i < 12; i++) {
            float4 f = *(const float4*)(xr + i * 4);
            vb[i*4] = f.x; vb[i*4+1] = f.y; vb[i*4+2] = f.z; vb[i*4+3] = f.w;
            s  += f.x + f.y + f.z + f.w;
            q2 += f.x*f.x + f.y*f.y + f.z*f.z + f.w*f.w;
        }
        s  += __shfl_xor_sync(0xFFFFFFFFu, s, 1);
        q2 += __shfl_xor_sync(0xFFFFFFFFu, q2, 1);
        float mu = s * (1.f / 96.f);
        float var = q2 * (1.f / 96.f) - mu * mu;
        float rs = rsqrtf(var + 1e-5f);
        #pragma unroll
        for (int j = 0; j < 48; j += 2) {
            int c = half * 48 + j;
            float n0 = (vb[j]   - mu) * rs * lnw[c]     + lnb[c];
            float n1 = (vb[j+1] - mu) * rs * lnw[c + 1] + lnb[c + 1];
            *(__nv_bfloat162*)(&As[r * PITCH + c]) = __floats2bfloat162_rn(n0, n1);
        }
    }

    const uint32_t smA = smem_u32(As), smB = smem_u32(Bs);
    const int t8 = lane & 7, tq = lane >> 3;
    const int rowA_base = warpM * 32 + t8 + (tq & 1) * 8;
    const int koffA = (tq >> 1) * 8;
    uint32_t offA[2];
    #pragma unroll
    for (int mf = 0; mf < 2; mf++)
        offA[mf] = smA + (uint32_t)(((rowA_base + mf * 16) * PITCH + koffA) * 2);
    const int rowB_base = warpN * 48 + t8 + (tq >> 1) * 8;
    const int koffB = (tq & 1) * 8;
    uint32_t offB[3];
    #pragma unroll
    for (int np = 0; np < 3; np++)
        offB[np] = smB + (uint32_t)(((rowB_base + np * 16) * PITCH + koffB) * 2);
    const int g = lane >> 2, tig = lane & 3;

    #pragma unroll
    for (int nc = 0; nc < NCH; nc++) {
        const int col0 = nc * 96;
        if (nc) __syncthreads();
        for (int idx = tid; idx < 96 * 12; idx += 256) {
            int n = idx / 12, k = (idx % 12) * 8;
            uint4 v = *(const uint4*)(W + (long)(col0 + n) * 96 + k);
            *(uint4*)(&Bs[n * PITCH + k]) = v;
        }
        __syncthreads();

        float acc[2][6][4];
        #pragma unroll
        for (int i = 0; i < 2; i++)
            #pragma unroll
            for (int j = 0; j < 6; j++)
                #pragma unroll
                for (int q = 0; q < 4; q++) acc[i][j][q] = 0.f;
        #pragma unroll
        for (int ks = 0; ks < 6; ks++) {
            uint32_t af[2][4], bf[3][4];
            ldsm_x4(af[0], offA[0] + ks * 32);
            ldsm_x4(af[1], offA[1] + ks * 32);
            ldsm_x4(bf[0], offB[0] + ks * 32);
            ldsm_x4(bf[1], offB[1] + ks * 32);
            ldsm_x4(bf[2], offB[2] + ks * 32);
            #pragma unroll
            for (int mf = 0; mf < 2; mf++)
                #pragma unroll
                for (int np = 0; np < 3; np++) {
                    mma16816(acc[mf][np * 2 + 0], af[mf], &bf[np][0]);
                    mma16816(acc[mf][np * 2 + 1], af[mf], &bf[np][2]);
                }
        }

        #pragma unroll
        for (int mf = 0; mf < 2; mf++) {
            #pragma unroll
            for (int nf = 0; nf < 6; nf++) {
                int col = col0 + warpN * 48 + nf * 8 + tig * 2;
                #pragma unroll
                for (int h = 0; h < 2; h++) {
                    long row = row0 + warpM * 32 + mf * 16 + g + h * 8;
                    float v0 = acc[mf][nf][h * 2 + 0];
                    float v1 = acc[mf][nf][h * 2 + 1];
                    if (EPI == 3) {
                        if (bias) { v0 += bias[col]; v1 += bias[col + 1]; }
                        const float2 rr = *(const float2*)(resid + row * NOtot + col);
                        v0 += rr.x; v1 += rr.y;
                        *(float2*)((float*)outv + row * NOtot + col) = make_float2(v0, v1);
                        *(__nv_bfloat162*)(out2 + row * NOtot + col) = __floats2bfloat162_rn(v0, v1);
                    } else {
                        *(__nv_bfloat162*)((__nv_bfloat16*)outv + row * NOtot + col) = __floats2bfloat162_rn(v0, v1);
                    }
                }
            }
        }
    }
}

// ---------------- multi-dilate local attention (vectorized bf16) ------------
__global__ void attn_kernel(const __nv_bfloat16* __restrict__ qkv, __nv_bfloat16* __restrict__ outb) {
    __shared__ __align__(16) __nv_bfloat16 ks[98 * 32];
    __shared__ __align__(16) __nv_bfloat16 vs[98 * 32];
    __shared__ int toks[98];
    int win = blockIdx.x;
    int dil = blockIdx.y + 1;
    int choff = blockIdx.y * 32;
    int tid = threadIdx.x;
    if (tid < 98) {
        int b  = win >> 9;
        int dq = (win >> 6) & 7;
        int hq = (win >> 3) & 7;
        int wq = win & 7;
        int wd = tid / 49, rem = tid % 49;
        int wh = rem / 7, ww = rem % 7;
        int d = dq * 2 + wd, h = hq * 7 + wh, w = wq * 7 + ww;
        toks[tid] = ((b * 16 + d) * 56 + h) * 56 + w;
    }
    __syncthreads();
    for (int idx = tid; idx < 98 * 8; idx += 224) {
        int n = idx >> 3, sub = idx & 7;
        int isv = sub >> 2, c8 = (sub & 3) * 8;
        long base = (long)toks[n] * 288 + choff + (isv ? 192 : 96) + c8;
        uint4 v = *(const uint4*)(qkv + base);
        *(uint4*)((isv ? vs : ks) + n * 32 + c8) = v;
    }
    __syncthreads();
    if (tid < 196) {
        int n = tid >> 1, head = tid & 1;
        long qbase = (long)toks[n] * 288 + choff + head * 16;
        float q[16];
        {
            uint4 qa = *(const uint4*)(qkv + qbase);
            uint4 qb = *(const uint4*)(qkv + qbase + 8);
            const __nv_bfloat162* qp = (const __nv_bfloat162*)&qa;
            #pragma unroll
            for (int i = 0; i < 4; i++) {
                float2 f = __bfloat1622float2(qp[i]);
                q[i * 2] = f.x; q[i * 2 + 1] = f.y;
            }
            qp = (const __nv_bfloat162*)&qb;
            #pragma unroll
            for (int i = 0; i < 4; i++) {
                float2 f = __bfloat1622float2(qp[i]);
                q[8 + i * 2] = f.x; q[8 + i * 2 + 1] = f.y;
            }
        }
        float lr[3]; int mm[3];
        #pragma unroll
        for (int j = 0; j < 3; j++) {
            int m = n + (j - 1) * dil;
            mm[j] = m;
            float s = 0.f;
            if (m >= 0 && m < 98) {
                const __nv_bfloat162* kr = (const __nv_bfloat162*)&ks[m * 32 + head * 16];
                #pragma unroll
                for (int c = 0; c < 8; c++) {
                    float2 f = __bfloat1622float2(kr[c]);
                    s += q[c * 2] * f.x + q[c * 2 + 1] * f.y;
                }
            }
            lr[j] = s * 0.25f;
        }
        float mx = fmaxf(0.f, fmaxf(lr[0], fmaxf(lr[1], lr[2])));
        float e[3];
        e[0] = expf(lr[0] - mx); e[1] = expf(lr[1] - mx); e[2] = expf(lr[2] - mx);
        float denom = 6.f * expf(-mx) + e[0] + e[1] + e[2];
        float o[16];
        #pragma unroll
        for (int c = 0; c < 16; c++) o[c] = 0.f;
        #pragma unroll
        for (int j = 0; j < 3; j++) {
            int m = mm[j];
            if (m >= 0 && m < 98) {
                float a = e[j] / denom;
                const __nv_bfloat162* vr = (const __nv_bfloat162*)&vs[m * 32 + head * 16];
                #pragma unroll
                for (int c = 0; c < 8; c++) {
                    float2 f = __bfloat1622float2(vr[c]);
                    o[c * 2]     += a * f.x;
                    o[c * 2 + 1] += a * f.y;
                }
            }
        }
        long obase = (long)toks[n] * 96 + choff + head * 16;
        #pragma unroll
        for (int c = 0; c < 8; c++)
            *(__nv_bfloat162*)(outb + obase + c * 2) = __floats2bfloat162_rn(o[c * 2], o[c * 2 + 1]);
    }
}

// ---------------- fused convp + LN2 + MLP ------------------------------------
// Phase A: x2 = x1 + relu(GN(conv)) @ wc^T ; xn = LN2(x2) -> As (smem)
// Phase B: out = x2 + gelu(xn @ w1^T + b1) @ w2^T + b2
__global__ __launch_bounds__(256, 2)
void convpfc_kernel(const __nv_bfloat16* __restrict__ convb, const __nv_bfloat16* __restrict__ wc,
                    const float* __restrict__ stats, const float* __restrict__ gnw,
                    const float* __restrict__ gnb, const float* __restrict__ x1,
                    const float* __restrict__ n2w, const float* __restrict__ n2b,
                    const __nv_bfloat16* __restrict__ w1, const __nv_bfloat16* __restrict__ w2,
                    const float* __restrict__ b1, const float* __restrict__ b2,
                    float* __restrict__ x2, float* __restrict__ out) {
    constexpr int PITCH = 104;
    extern __shared__ __align__(16) char sm[];
    __nv_bfloat16* As  = (__nv_bfloat16*)sm;                 // 26624B (GN input, then xn)
    __nv_bfloat16* Bs1 = (__nv_bfloat16*)(sm + 26624);       // 19968B (wc, then w1 chunks)
    __nv_bfloat16* Bs2 = (__nv_bfloat16*)(sm + 46592);       // 19968B (w2 chunks)
    __nv_bfloat16* Hs  = (__nv_bfloat16*)(sm + 66560);       // 26624B (gelu hidden)
    __shared__ float redS[128][2], redQ[128][2];
    const int tid = threadIdx.x;
    const int wid = tid >> 5, lane = tid & 31;
    const int warpM = wid & 3, warpN = wid >> 2;
    const long row0 = (long)blockIdx.x * 128;

    // ---- Phase A prologue: GN+ReLU -> As ; wc -> Bs1 ----
    const int bidx = (int)(row0 / 50176) * 4;
    for (int idx = tid; idx < 128 * 12; idx += 256) {
        int r = idx / 12, k8 = (idx % 12) * 8;
        uint4 cv = *(const uint4*)(convb + (row0 + r) * 96 + k8);
        const __nv_bfloat16* cp = (const __nv_bfloat16*)&cv;
        int gi = bidx + k8 / 24;
        float mu = stats[gi * 2], rs = stats[gi * 2 + 1];
        #pragma unroll
        for (int j = 0; j < 8; j += 2) {
            int c = k8 + j;
            float f0 = fmaxf((__bfloat162float(cp[j])     - mu) * rs * gnw[c]     + gnb[c],     0.f);
            float f1 = fmaxf((__bfloat162float(cp[j + 1]) - mu) * rs * gnw[c + 1] + gnb[c + 1], 0.f);
            *(__nv_bfloat162*)(&As[r * PITCH + c]) = __floats2bfloat162_rn(f0, f1);
        }
    }
    for (int idx = tid; idx < 96 * 12; idx += 256) {
        int n = idx / 12, k = (idx % 12) * 8;
        uint4 v = *(const uint4*)(wc + n * 96 + k);
        *(uint4*)(&Bs1[n * PITCH + k]) = v;
    }
    __syncthreads();

    const uint32_t smA = smem_u32(As), smB1 = smem_u32(Bs1), smB2 = smem_u32(Bs2), smH = smem_u32(Hs);
    const int t8 = lane & 7, tq = lane >> 3;
    const int rowA_base = warpM * 32 + t8 + (tq & 1) * 8;
    const int koffA = (tq >> 1) * 8;
    uint32_t offA[2], offH[2];
    #pragma unroll
    for (int mf = 0; mf < 2; mf++) {
        offA[mf] = smA + (uint32_t)(((rowA_base + mf * 16) * PITCH + koffA) * 2);
        offH[mf] = smH + (uint32_t)(((rowA_base + mf * 16) * PITCH + koffA) * 2);
    }
    const int rowB_base = warpN * 48 + t8 + (tq >> 1) * 8;
    const int koffB = (tq & 1) * 8;
    uint32_t offB1[3], offB2[3];
    #pragma unroll
    for (int np = 0; np < 3; np++) {
        offB1[np] = smB1 + (uint32_t)(((rowB_base + np * 16) * PITCH + koffB) * 2);
        offB2[np] = smB2 + (uint32_t)(((rowB_base + np * 16) * PITCH + koffB) * 2);
    }
    const int g = lane >> 2, tig = lane & 3;

    // ---- Phase A GEMM ----
    float acc[2][6][4];
    #pragma unroll
    for (int i = 0; i < 2; i++)
        #pragma unroll
        for (int j = 0; j < 6; j++)
            #pragma unroll
            for (int q = 0; q < 4; q++) acc[i][j][q] = 0.f;
    #pragma unroll
    for (int ks = 0; ks < 6; ks++) {
        uint32_t af[2][4], bf[3][4];
        ldsm_x4(af[0], offA[0] + ks * 32);
        ldsm_x4(af[1], offA[1] + ks * 32);
        ldsm_x4(bf[0], offB1[0] + ks * 32);
        ldsm_x4(bf[1], offB1[1] + ks * 32);
        ldsm_x4(bf[2], offB1[2] + ks * 32);
        #pragma unroll
        for (int mf = 0; mf < 2; mf++)
            #pragma unroll
            for (int np = 0; np < 3; np++) {
                mma16816(acc[mf][np * 2 + 0], af[mf], &bf[np][0]);
                mma16816(acc[mf][np * 2 + 1], af[mf], &bf[np][2]);
            }
    }

    // ---- Phase A epilogue: residual + row stats ----
    #pragma unroll
    for (int mf = 0; mf < 2; mf++)
        #pragma unroll
        for (int h = 0; h < 2; h++) {
            int rl = warpM * 32 + mf * 16 + g + h * 8;
            long row = row0 + rl;
            float s = 0.f, q2 = 0.f;
            #pragma unroll
            for (int nf = 0; nf < 6; nf++) {
                int col = warpN * 48 + nf * 8 + tig * 2;
                const float2 rr = *(const float2*)(x1 + row * 96 + col);
                float v0 = acc[mf][nf][h * 2 + 0] + rr.x;
                float v1 = acc[mf][nf][h * 2 + 1] + rr.y;
                acc[mf][nf][h * 2 + 0] = v0;
                acc[mf][nf][h * 2 + 1] = v1;
                s += v0 + v1; q2 += v0 * v0 + v1 * v1;
            }
            s  += __shfl_xor_sync(0xFFFFFFFFu, s, 1);
            q2 += __shfl_xor_sync(0xFFFFFFFFu, q2, 1);
            s  += __shfl_xor_sync(0xFFFFFFFFu, s, 2);
            q2 += __shfl_xor_sync(0xFFFFFFFFu, q2, 2);
            if (tig == 0) { redS[rl][warpN] = s; redQ[rl][warpN] = q2; }
        }
    __syncthreads();   // stats ready; all Phase-A ldsm reads of As complete

    // ---- LN2: write x2 global, xn -> As ----
    #pragma unroll
    for (int mf = 0; mf < 2; mf++)
        #pragma unroll
        for (int h = 0; h < 2; h++) {
            int rl = warpM * 32 + mf * 16 + g + h * 8;
            long row = row0 + rl;
            float tot = redS[rl][0] + redS[rl][1];
            float tq2 = redQ[rl][0] + redQ[rl][1];
            float mu = tot * (1.f / 96.f);
            float var = tq2 * (1.f / 96.f) - mu * mu;
            float rs = rsqrtf(var + 1e-5f);
            #pragma unroll
            for (int nf = 0; nf < 6; nf++) {
                int col = warpN * 48 + nf * 8 + tig * 2;
                float v0 = acc[mf][nf][h * 2 + 0];
                float v1 = acc[mf][nf][h * 2 + 1];
                *(float2*)(x2 + row * 96 + col) = make_float2(v0, v1);
                float n0 = (v0 - mu) * rs * n2w[col]     + n2b[col];
                float n1 = (v1 - mu) * rs * n2w[col + 1] + n2b[col + 1];
                *(__nv_bfloat162*)(&As[rl * PITCH + col]) = __floats2bfloat162_rn(n0, n1);
            }
        }

    // ---- Phase B: MLP over 4 hidden chunks ----
    float acc2[2][6][4];
    #pragma unroll
    for (int i = 0; i < 2; i++)
        #pragma unroll
        for (int j = 0; j < 6; j++)
            #pragma unroll
            for (int q = 0; q < 4; q++) acc2[i][j][q] = 0.f;

    for (int nc = 0; nc < 4; nc++) {
        __syncthreads();   // As/xn visible (nc=0); prior Bs readers done
        for (int idx = tid; idx < 96 * 12; idx += 256) {
            int n = idx / 12, k = (idx % 12) * 8;
            uint4 v1 = *(const uint4*)(w1 + (long)(nc * 96 + n) * 96 + k);
            *(uint4*)(&Bs1[n * PITCH + k]) = v1;
            uint4 v2 = *(const uint4*)(w2 + (long)n * 384 + nc * 96 + k);
            *(uint4*)(&Bs2[n * PITCH + k]) = v2;
        }
        __syncthreads();

        float acc1[2][6][4];
        #pragma unroll
        for (int i = 0; i < 2; i++)
            #pragma unroll
            for (int j = 0; j < 6; j++)
                #pragma unroll
                for (int q = 0; q < 4; q++) acc1[i][j][q] = 0.f;
        #pragma unroll
        for (int ks = 0; ks < 6; ks++) {
            uint32_t af[2][4], bf[3][4];
            ldsm_x4(af[0], offA[0] + ks * 32);
            ldsm_x4(af[1], offA[1] + ks * 32);
            ldsm_x4(bf[0], offB1[0] + ks * 32);
            ldsm_x4(bf[1], offB1[1] + ks * 32);
            ldsm_x4(bf[2], offB1[2] + ks * 32);
            #pragma unroll
            for (int mf = 0; mf < 2; mf++)
                #pragma unroll
                for (int np = 0; np < 3; np++) {
                    mma16816(acc1[mf][np * 2 + 0], af[mf], &bf[np][0]);
                    mma16816(acc1[mf][np * 2 + 1], af[mf], &bf[np][2]);
                }
        }
        #pragma unroll
        for (int mf = 0; mf < 2; mf++)
            #pragma unroll
            for (int nf = 0; nf < 6; nf++) {
                int hcol = warpN * 48 + nf * 8 + tig * 2;
                float bb0 = b1[nc * 96 + hcol], bb1 = b1[nc * 96 + hcol + 1];
                #pragma unroll
                for (int h = 0; h < 2; h++) {
                    int rl = warpM * 32 + mf * 16 + g + h * 8;
                    float v0 = gelu_exact(acc1[mf][nf][h * 2 + 0] + bb0);
                    float v1 = gelu_exact(acc1[mf][nf][h * 2 + 1] + bb1);
                    *(__nv_bfloat162*)(&Hs[rl * PITCH + hcol]) = __floats2bfloat162_rn(v0, v1);
                }
            }
        __syncthreads();

        #pragma unroll
        for (int ks = 0; ks < 6; ks++) {
            uint32_t af[2][4], bf[3][4];
            ldsm_x4(af[0], offH[0] + ks * 32);
            ldsm_x4(af[1], offH[1] + ks * 32);
            ldsm_x4(bf[0], offB2[0] + ks * 32);
            ldsm_x4(bf[1], offB2[1] + ks * 32);
            ldsm_x4(bf[2], offB2[2] + ks * 32);
            #pragma unroll
            for (int mf = 0; mf < 2; mf++)
                #pragma unroll
                for (int np = 0; np < 3; np++) {
                    mma16816(acc2[mf][np * 2 + 0], af[mf], &bf[np][0]);
                    mma16816(acc2[mf][np * 2 + 1], af[mf], &bf[np][2]);
                }
        }
    }

    // ---- final epilogue: out = acc2 + b2 + x2 (x2 L2-resident) ----
    #pragma unroll
    for (int mf = 0; mf < 2; mf++)
        #pragma unroll
        for (int nf = 0; nf < 6; nf++) {
            int col = warpN * 48 + nf * 8 + tig * 2;
            #pragma unroll
            for (int h = 0; h < 2; h++) {
                long row = row0 + warpM * 32 + mf * 16 + g + h * 8;
                const float2 rr = *(const float2*)(x2 + row * 96 + col);
                float v0 = acc2[mf][nf][h * 2 + 0] + b2[col]     + rr.x;
                float v1 = acc2[mf][nf][h * 2 + 1] + b2[col + 1] + rr.y;
                *(float2*)(out + row * 96 + col) = make_float2(v0, v1);
            }
        }
}

// ---------------- tensor-core grouped 3x3x3 conv (256 thr, pipelined) -------
#define CVP 40
#define WP3 872
__global__ __launch_bounds__(256)
void conv3t_kernel(const __nv_bfloat16* __restrict__ x, const __nv_bfloat16* __restrict__ wc3,
                   __nv_bfloat16* __restrict__ o, float* __restrict__ part2) {
    extern __shared__ __align__(16) char smc[];
    __nv_bfloat16* ws   = (__nv_bfloat16*)smc;
    __nv_bfloat16* in_s = (__nv_bfloat16*)(smc + 32 * WP3 * 2);
    __shared__ float redg[4][256];
    int bid = blockIdx.x;
    int g = bid % 3; int t = bid / 3;
    int tw = t % 7, th = (t / 7) % 7, b = t / 49;
    int h0 = th * 8, w0 = tw * 8;
    int tid = threadIdx.x, wid = tid >> 5, lane = tid & 31;
    const int wrp2 = wid & 3;
    const int ch   = wid >> 2;

    for (int idx = tid; idx < 32 * 108; idx += 256) {
        int row = idx / 108, kc = (idx % 108) * 8;
        uint4 v = *(const uint4*)(wc3 + (g * 32 + row) * 864 + kc);
        *(uint4*)(ws + row * WP3 + kc) = v;
    }

    const int pos0 = tid >> 2,          c80 = (tid & 3) * 8;
    const int hh0 = pos0 / 10,          ww0s = pos0 % 10;
    const int ih0 = h0 - 1 + hh0,       iw0 = w0 - 1 + ww0s;
    const bool ok0xy = (ih0 >= 0 && ih0 < 56 && iw0 >= 0 && iw0 < 56);
    const int tid2 = tid + 256;
    const int pos1 = tid2 >> 2,         c81 = (tid2 & 3) * 8;
    const int hh1 = pos1 / 10,          ww1s = pos1 % 10;
    const int ih1 = h0 - 1 + hh1,       iw1 = w0 - 1 + ww1s;
    const bool have1 = (tid2 < 400);
    const bool ok1xy = have1 && (ih1 >= 0 && ih1 < 56 && iw1 >= 0 && iw1 < 56);

    auto load_plane = [&](int dde, int slot) {
        uint4 v = make_uint4(0, 0, 0, 0);
        if (dde >= 0 && dde < 16 && ok0xy)
            v = *(const uint4*)(x + ((long)((b * 16 + dde) * 56 + ih0) * 56 + iw0) * 96 + g * 32 + c80);
        *(uint4*)(in_s + slot * 4000 + (hh0 * 10 + ww0s) * CVP + c80) = v;
        if (have1) {
            uint4 v2 = make_uint4(0, 0, 0, 0);
            if (dde >= 0 && dde < 16 && ok1xy)
                v2 = *(const uint4*)(x + ((long)((b * 16 + dde) * 56 + ih1) * 56 + iw1) * 96 + g * 32 + c81);
            *(uint4*)(in_s + slot * 4000 + (hh1 * 10 + ww1s) * CVP + c81) = v2;
        }
    };
    load_plane(-1, 2);
    load_plane(0,  0);
    load_plane(1,  1);

    const int t8 = lane & 7, tq = lane >> 3;
    const int mrow = t8 + (tq & 1) * 8;
    const int p = wrp2 * 16 + mrow;
    const int hr = p >> 3, wc = p & 7;
    const int koffA = (tq >> 1) * 8;
    const uint32_t inb = smem_u32(in_s);
    const uint32_t aoff = inb + (uint32_t)(((hr * 10 + wc) * CVP + koffA) * 2);
    const int nr = ch * 16 + t8 + (tq >> 1) * 8;
    const int koffB = (tq & 1) * 8;
    const uint32_t wsb = smem_u32(ws);
    const uint32_t boff = wsb + (uint32_t)((nr * WP3 + koffB) * 2);
    const int g2 = lane >> 2, tig = lane & 3;
    const int nf_thresh = 3 - g;

    float gnS[2] = {0.f, 0.f}, gnQ[2] = {0.f, 0.f};
    __syncthreads();

    for (int dcur = 0; dcur < 16; dcur++) {
        uint4 pre0 = make_uint4(0, 0, 0, 0), pre1 = make_uint4(0, 0, 0, 0);
        {
            int dde = dcur + 2;
            if (dde < 16 && ok0xy)
                pre0 = *(const uint4*)(x + ((long)((b * 16 + dde) * 56 + ih0) * 56 + iw0) * 96 + g * 32 + c80);
            if (dde < 16 && ok1xy)
                pre1 = *(const uint4*)(x + ((long)((b * 16 + dde) * 56 + ih1) * 56 + iw1) * 96 + g * 32 + c81);
        }

        int slots[3] = { (dcur + 2) % 3, dcur % 3, (dcur + 1) % 3 };

        float acc[2][2][4];
        #pragma unroll
        for (int i = 0; i < 2; i++)
            #pragma unroll
            for (int s2 = 0; s2 < 2; s2++)
                #pragma unroll
                for (int q = 0; q < 4; q++) acc[i][s2][q] = 0.f;

        #pragma unroll
        for (int kd = 0; kd < 3; kd++)
            #pragma unroll
            for (int kh = 0; kh < 3; kh++)
                #pragma unroll
                for (int kw = 0; kw < 3; kw++) {
                    uint32_t abase = aoff + (uint32_t)((slots[kd] * 4000 + (kh * 10 + kw) * CVP) * 2);
                    int tap = kd * 9 + kh * 3 + kw;
                    #pragma unroll
                    for (int s = 0; s < 2; s++) {
                        uint32_t af[4], bfr[4];
                        ldsm_x4(af, abase + s * 32);
                        ldsm_x4(bfr, boff + (uint32_t)((tap * 32 + s * 16) * 2));
                        mma16816(acc[0][s], af, &bfr[0]);
                        mma16816(acc[1][s], af, &bfr[2]);
                    }
                }

        #pragma unroll
        for (int hbit = 0; hbit < 2; hbit++) {
            long tok = ((long)(b * 16 + dcur) * 56 + (h0 + 2 * wrp2 + hbit)) * 56 + (w0 + g2);
            __nv_bfloat16* orow = o + tok * 96 + g * 32 + ch * 16;
            #pragma unroll
            for (int nf = 0; nf < 2; nf++) {
                int co = nf * 8 + tig * 2;
                float v0 = acc[nf][0][hbit * 2]     + acc[nf][1][hbit * 2];
                float v1 = acc[nf][0][hbit * 2 + 1] + acc[nf][1][hbit * 2 + 1];
                *(__nv_bfloat162*)(orow + co) = __floats2bfloat162_rn(v0, v1);
                int bkt = ((ch * 2 + nf) >= nf_thresh) ? 1 : 0;
                gnS[bkt] += v0 + v1;
                gnQ[bkt] += v0 * v0 + v1 * v1;
            }
        }

        __syncthreads();
        {
            int slot = (dcur + 2) % 3;
            *(uint4*)(in_s + slot * 4000 + (hh0 * 10 + ww0s) * CVP + c80) = pre0;
            if (have1)
                *(uint4*)(in_s + slot * 4000 + (hh1 * 10 + ww1s) * CVP + c81) = pre1;
        }
        __syncthreads();
    }

    redg[0][tid] = gnS[0]; redg[1][tid] = gnQ[0];
    redg[2][tid] = gnS[1]; redg[3][tid] = gnQ[1];
    __syncthreads();
    for (int off = 128; off; off >>= 1) {
        if (tid < off) {
            #pragma unroll
            for (int j = 0; j < 4; j++) redg[j][tid] += redg[j][tid + off];
        }
        __syncthreads();
    }
    if (tid == 0) {
        part2[bid * 4 + 0] = redg[0][0];
        part2[bid * 4 + 1] = redg[1][0];
        part2[bid * 4 + 2] = redg[2][0];
        part2[bid * 4 + 3] = redg[3][0];
    }
}

// ---------------- GN stats combine (deterministic, from conv partials) ------
__global__ void gncomb_kernel(const float* __restrict__ part2, float* __restrict__ stats) {
    int t = threadIdx.x;
    if (t < 16) {
        int b = t >> 2, gi = t & 3;
        int gA = -1, kA = 0, gB = -1, kB = 0;
        if (gi == 0) { gA = 0; kA = 0; }
        else if (gi == 1) { gA = 0; kA = 1; gB = 1; kB = 0; }
        else if (gi == 2) { gA = 1; kA = 1; gB = 2; kB = 0; }
        else { gA = 2; kA = 1; }
        double s = 0.0, q2 = 0.0;
        for (int tile = 0; tile < 49; tile++) {
            int base = ((b * 49 + tile) * 3 + gA) * 4 + kA * 2;
            s += (double)part2[base]; q2 += (double)part2[base + 1];
        }
        if (gB >= 0) {
            for (int tile = 0; tile < 49; tile++) {
                int base = ((b * 49 + tile) * 3 + gB) * 4 + kB * 2;
                s += (double)part2[base]; q2 += (double)part2[base + 1];
            }
        }
        double N = 24.0 * 50176.0;
        double mu  = s / N;
        double var = q2 / N - mu * mu;
        stats[t * 2]     = (float)mu;
        stats[t * 2 + 1] = (float)(1.0 / sqrt(var + 1e-5));
    }
}

// ---------------- merged weight prep ----------------------------------------
__global__ void prep_kernel(const float* __restrict__ qkv_w, const float* __restrict__ proj_w,
                            const float* __restrict__ convp_w, const float* __restrict__ fc1_w,
                            const float* __restrict__ fc2_w, const float* __restrict__ conv3_w,
                            __nv_bfloat16* wq, __nv_bfloat16* wp, __nv_bfloat16* wc,
                            __nv_bfloat16* w1, __nv_bfloat16* w2, __nv_bfloat16* wc3) {
    int i = blockIdx.x * 256 + threadIdx.x;
    if (i < 27648) { wq[i] = __float2bfloat16(qkv_w[i]); return; }
    i -= 27648;
    if (i < 9216)  { wp[i] = __float2bfloat16(proj_w[i]); return; }
    i -= 9216;
    if (i < 9216)  { wc[i] = __float2bfloat16(convp_w[i]); return; }
    i -= 9216;
    if (i < 36864) { w1[i] = __float2bfloat16(fc1_w[i]); return; }
    i -= 36864;
    if (i < 36864) { w2[i] = __float2bfloat16(fc2_w[i]); return; }
    i -= 36864;
    if (i < 82944) {
        int co = i / 864, r = i % 864;
        int tap = r >> 5, ci = r & 31;
        wc3[i] = __float2bfloat16(conv3_w[co * 864 + ci * 27 + tap]);
    }
}

// ---------------- driver -----------------------------------------------------
extern "C" void kernel_launch(void* const* d_in, const int* in_sizes, int n_in,
                              void* d_out, int out_size) {
    const float* x       = (const float*)d_in[0];
    const float* n1w     = (const float*)d_in[1];
    const float* n1b     = (const float*)d_in[2];
    const float* qkv_w   = (const float*)d_in[3];
    const float* proj_w  = (const float*)d_in[4];
    const float* proj_b  = (const float*)d_in[5];
    const float* conv3_w = (const float*)d_in[6];
    const float* gn_w    = (const float*)d_in[7];
    const float* gn_b    = (const float*)d_in[8];
    const float* convp_w = (const float*)d_in[9];
    const float* n2w     = (const float*)d_in[10];
    const float* n2b     = (const float*)d_in[11];
    const float* fc1_w   = (const float*)d_in[12];
    const float* fc1_b   = (const float*)d_in[13];
    const float* fc2_w   = (const float*)d_in[14];
    const float* fc2_b   = (const float*)d_in[15];
    float* out = (float*)d_out;

    float *p_x1, *p_x2, *p_part2, *p_stats;
    __nv_bfloat16 *p_convb, *p_qkvb, *p_attb, *p_x1b;
    __nv_bfloat16 *p_wq, *p_wp, *p_wc, *p_w1, *p_w2, *p_wc3;
    cudaGetSymbolAddress((void**)&p_x1,   g_x1);
    cudaGetSymbolAddress((void**)&p_x2,   g_x2);
    cudaGetSymbolAddress((void**)&p_part2,g_part2);
    cudaGetSymbolAddress((void**)&p_stats,g_stats);
    cudaGetSymbolAddress((void**)&p_convb,g_convb);
    cudaGetSymbolAddress((void**)&p_qkvb, g_qkvb);
    cudaGetSymbolAddress((void**)&p_attb, g_attb);
    cudaGetSymbolAddress((void**)&p_x1b,  g_x1b);
    cudaGetSymbolAddress((void**)&p_wq,   g_wq);
    cudaGetSymbolAddress((void**)&p_wp,   g_wp);
    cudaGetSymbolAddress((void**)&p_wc,   g_wc);
    cudaGetSymbolAddress((void**)&p_w1,   g_w1);
    cudaGetSymbolAddress((void**)&p_w2,   g_w2);
    cudaGetSymbolAddress((void**)&p_wc3,  g_wc3);

    const int CONV_SMEM = 32 * WP3 * 2 + 3 * 4000 * 2;   // 79808
    const int CF_SMEM   = 26624 + 19968 + 19968 + 26624; // 93184
    cudaFuncSetAttribute(conv3t_kernel,  cudaFuncAttributeMaxDynamicSharedMemorySize, CONV_SMEM);
    cudaFuncSetAttribute(convpfc_kernel, cudaFuncAttributeMaxDynamicSharedMemorySize, CF_SMEM);

    // 0) merged weight prep
    prep_kernel<<<(202752 + 255) / 256, 256>>>(qkv_w, proj_w, convp_w, fc1_w, fc2_w, conv3_w,
                                               p_wq, p_wp, p_wc, p_w1, p_w2, p_wc3);
    // 1) qkv = LN1(x) @ qkv_w^T -> bf16
    tgemm<3,4,1><<<1568, 256>>>(x, p_wq, nullptr, nullptr, p_qkvb, nullptr, n1w, n1b);
    // 2) attention (vectorized bf16)
    attn_kernel<<<dim3(2048, 3), 224>>>(p_qkvb, p_attb);
    // 3) x1 = x + attn @ proj_w^T + proj_b
    tgemm<1,3,0><<<1568, 256>>>(p_attb, p_wp, proj_b, x, p_x1, p_x1b, nullptr, nullptr);
    // 4) grouped conv (pipelined prefetch, s-split accumulators, bf16 out)
    conv3t_kernel<<<588, 256, CONV_SMEM>>>(p_x1b, p_wc3, p_convb, p_part2);
    // 5) GN stats combine (deterministic)
    gncomb_kernel<<<1, 16>>>(p_part2, p_stats);
    // 6) fused: convp(GN+ReLU -> 1x1 conv + resid) + LN2 + MLP -> out
    convpfc_kernel<<<1568, 256, CF_SMEM>>>(p_convb, p_wc, p_stats, gn_w, gn_b, p_x1,
                                           n2w, n2b, p_w1, p_w2, fc1_b, fc2_b, p_x2, out);
}